// round 14
// baseline (speedup 1.0000x reference)
#include <cuda_runtime.h>
#include <math.h>
#include <stdint.h>

// ---------------- problem constants ----------------
#define BATCH 8
#define SEQ   1024
#define DIM   768
#define HEADS 8
#define HDIM  96
#define KNEIGH 5
#define NLAYERS 3
#define ROWS (BATCH*SEQ)  // 8192
#define LN_EPS 1e-5f

// ---------------- device scratch (static, allocation-free) ----------------
__device__ float g_h[ROWS * DIM];
__device__ float g_xw[ROWS * DIM];
__device__ float g_qkv[ROWS * 3 * DIM];
__device__ float g_scores[(long long)BATCH * SEQ * SEQ]; // sim workspace (32 MB)
__device__ float g_cat[ROWS * 2 * DIM];   // [gcn | attn] stride 1536 (fp32 for fuse_ln)
__device__ float g_gate[ROWS * DIM];
__device__ unsigned char g_adj[(long long)BATCH * SEQ * SEQ];    // 8 MB
__device__ float g_dinv[ROWS];
__device__ int   g_topk[ROWS * KNEIGH];
__device__ uint32_t g_wp[6488064];         // fp16 fragment-packed weights (26 MB)
__device__ uint32_t g_ap[12582912];        // fp16 fragment-packed activations (50 MB)

// A-blob regions inside g_ap (words)
#define AP_H   0L
#define AP_O   3145728L
#define AP_CAT 6291456L

// packed weight word offsets
#define WP_FUSED(l) ((long)(l) * 1179648)
#define WP_AOW(l)   (3538944L + (long)(l) * 294912L)
#define WP_GW(l)    (4423680L + (long)(l) * 589824L)
#define WP_PROJ     (6193152L)

__device__ __forceinline__ uint32_t pack_h2(float a, float b) {
    uint32_t r;
    asm("cvt.rn.f16x2.f32 %0, %2, %1;" : "=r"(r) : "f"(a), "f"(b));
    return r;
}
__device__ __forceinline__ float h2f_lo(uint32_t h) {
    float f;
    asm("{.reg .b16 lo, hi;\n\t"
        "mov.b32 {lo, hi}, %1;\n\t"
        "cvt.f32.f16 %0, lo;}" : "=f"(f) : "r"(h));
    return f;
}
__device__ __forceinline__ float h2f_hi(uint32_t h) {
    float f;
    asm("{.reg .b16 lo, hi;\n\t"
        "mov.b32 {lo, hi}, %1;\n\t"
        "cvt.f32.f16 %0, hi;}" : "=f"(f) : "r"(h));
    return f;
}

// FMA-only exp (no MUFU)
__device__ __forceinline__ float fexp(float x) {
    x = fmaxf(x, -87.0f);
    float y = x * 1.4426950408889634f;
    int i = __float2int_rn(y);
    float r = (y - (float)i) * 0.6931471805599453f;
    float p = 1.9841270e-4f;
    p = fmaf(p, r, 1.3888889e-3f);
    p = fmaf(p, r, 8.3333333e-3f);
    p = fmaf(p, r, 4.1666667e-2f);
    p = fmaf(p, r, 1.6666667e-1f);
    p = fmaf(p, r, 0.5f);
    p = fmaf(p, r, 1.0f);
    p = fmaf(p, r, 1.0f);
    return p * __int_as_float((i + 127) << 23);
}

#define MMAF16(d, a, b) \
    asm volatile("mma.sync.aligned.m16n8k16.row.col.f32.f16.f16.f32 " \
        "{%0,%1,%2,%3}, {%4,%5,%6,%7}, {%8,%9}, {%0,%1,%2,%3};" \
        : "+f"((d)[0]), "+f"((d)[1]), "+f"((d)[2]), "+f"((d)[3]) \
        : "r"((a).x), "r"((a).y), "r"((a).z), "r"((a).w), \
          "r"((b).x), "r"((b).y))

// ---------------- batched weight packing: all 13 matrices in one launch ----------------
#define NREG 13
struct PackTable {
    const float* w[NREG];
    long wpOff[NREG];
    int  N[NREG];
    int  K[NREG];
    long pref[NREG + 1];   // prefix sums of word counts
};

__global__ void pack_all_weights(PackTable tab) {
    long total = tab.pref[NREG];
    for (long gid = (long)blockIdx.x * blockDim.x + threadIdx.x; gid < total;
         gid += (long)gridDim.x * blockDim.x) {
        int ri = 0;
        #pragma unroll
        for (int i = 0; i < NREG; i++)
            if (gid >= tab.pref[i + 1]) ri = i + 1;
        long wr = gid - tab.pref[ri];
        int N = tab.N[ri], K = tab.K[ri];
        int nch = K >> 5;
        long blk = wr >> 11;
        int widx = (int)(wr & 2047);
        int nblk = (int)(blk / nch), kch = (int)(blk % nch);
        int k8 = widx & 1;
        int rest = widx >> 1;
        int t = rest & 3, nn = (rest >> 2) & 7;
        int upper = rest >> 5;
        int k16 = upper & 1, in8 = upper >> 1;
        int n = nblk * 128 + in8 * 8 + nn;
        int k = kch * 32 + k16 * 16 + k8 * 8 + t * 2;
        const float* w = tab.w[ri];
        float v0 = w[(long)k * N + n];
        float v1 = w[(long)(k + 1) * N + n];
        g_wp[tab.wpOff[ri] + wr] = pack_h2(v0, v1);
    }
}

// ---------------- activation packing (x at layer 0 only) ----------------
__global__ void pack_act_kernel(const float* __restrict__ act, uint32_t* __restrict__ blob,
                                int K) {
    int kch = blockIdx.x, mblk = blockIdx.y;
    int nch = gridDim.x;
    const float* a0 = act + (long)mblk * 128 * K + kch * 32;
    uint32_t* out = blob + ((long)mblk * nch + kch) * 2048;
    int tid = threadIdx.x;
    #pragma unroll
    for (int i = 0; i < 8; i++) {
        int w = tid + 256 * i;
        int c = w & 3, lanep = (w >> 2) & 31, ikf = (w >> 7) & 1, im = w >> 8;
        int r = im * 16 + (c & 1) * 8 + (lanep >> 2);
        int k = ikf * 16 + ((c >> 1) & 1) * 8 + (lanep & 3) * 2;
        float2 v = *(const float2*)(a0 + (long)r * K + k);
        out[w] = pack_h2(v.x, v.y);
    }
}

// ---------------- sim = x x^T via fp16 hi/lo split (verified R9) ----------------
__global__ __launch_bounds__(256, 2)
void sim_gemm(const float* __restrict__ x, float* __restrict__ scores) {
    __shared__ uint32_t sAh[2048], sAl[2048], sBh[2048], sBl[2048];
    int b = blockIdx.z;
    int m0 = blockIdx.y * 128, n0 = blockIdx.x * 128;
    int tid = threadIdx.x, lane = tid & 31, wid = tid >> 5;
    int wm = wid & 1, wn = wid >> 1;
    const float* Xm = x + (long)b * SEQ * DIM + (long)m0 * DIM;
    const float* Xn = x + (long)b * SEQ * DIM + (long)n0 * DIM;

    int aR[4], aQ[4], aBase[4];
    #pragma unroll
    for (int i = 0; i < 4; i++) {
        int idx = tid + 256 * i;
        int r = idx >> 3, q = idx & 7;
        aR[i] = r; aQ[i] = q;
        int im = r >> 4, g = r & 7, row8 = (r >> 3) & 1;
        int ikf = q >> 2, k8 = (q >> 1) & 1;
        aBase[i] = ((im * 2 + ikf) * 32 + g * 4) * 4 + k8 * 2 + row8 + 8 * (q & 1);
    }
    int bR[4], bQ[4], bBase[4];
    #pragma unroll
    for (int i = 0; i < 4; i++) {
        int idx = tid + 256 * i;
        int r = idx >> 3, q = idx & 7;
        bR[i] = r; bQ[i] = q;
        int in = r >> 3, nn = r & 7;
        int ikf = q >> 2, k8 = (q >> 1) & 1;
        bBase[i] = ((in * 2 + ikf) * 32 + nn * 4) * 2 + k8 + 4 * (q & 1);
    }

    float acc[4][4][4];
    #pragma unroll
    for (int i = 0; i < 4; i++)
        #pragma unroll
        for (int j = 0; j < 4; j++)
            #pragma unroll
            for (int c = 0; c < 4; c++) acc[i][j][c] = 0.f;

    for (int it = 0; it < DIM / 32; it++) {
        long koff = (long)it * 32;
        float4 va[4], vb[4];
        #pragma unroll
        for (int i = 0; i < 4; i++)
            va[i] = *(const float4*)(Xm + (long)aR[i] * DIM + koff + aQ[i] * 4);
        #pragma unroll
        for (int i = 0; i < 4; i++)
            vb[i] = *(const float4*)(Xn + (long)bR[i] * DIM + koff + bQ[i] * 4);
        __syncthreads();
        #pragma unroll
        for (int i = 0; i < 4; i++) {
            uint32_t h0 = pack_h2(va[i].x, va[i].y);
            uint32_t h1 = pack_h2(va[i].z, va[i].w);
            uint32_t l0 = pack_h2(va[i].x - h2f_lo(h0), va[i].y - h2f_hi(h0));
            uint32_t l1 = pack_h2(va[i].z - h2f_lo(h1), va[i].w - h2f_hi(h1));
            sAh[aBase[i]] = h0; sAh[aBase[i] + 4] = h1;
            sAl[aBase[i]] = l0; sAl[aBase[i] + 4] = l1;
        }
        #pragma unroll
        for (int i = 0; i < 4; i++) {
            uint32_t h0 = pack_h2(vb[i].x, vb[i].y);
            uint32_t h1 = pack_h2(vb[i].z, vb[i].w);
            uint32_t l0 = pack_h2(vb[i].x - h2f_lo(h0), vb[i].y - h2f_hi(h0));
            uint32_t l1 = pack_h2(vb[i].z - h2f_lo(h1), vb[i].w - h2f_hi(h1));
            sBh[bBase[i]] = h0; sBh[bBase[i] + 2] = h1;
            sBl[bBase[i]] = l0; sBl[bBase[i] + 2] = l1;
        }
        __syncthreads();
        #pragma unroll
        for (int ikf = 0; ikf < 2; ikf++) {
            uint2 bh[4], bl[4];
            #pragma unroll
            for (int j2 = 0; j2 < 4; j2++) {
                int o = (((wn * 4 + j2) * 2 + ikf) * 32 + lane) * 2;
                bh[j2] = *(const uint2*)&sBh[o];
                bl[j2] = *(const uint2*)&sBl[o];
            }
            #pragma unroll
            for (int i2 = 0; i2 < 4; i2++) {
                int o = (((wm * 4 + i2) * 2 + ikf) * 32 + lane) * 4;
                uint4 ah = *(const uint4*)&sAh[o];
                uint4 al = *(const uint4*)&sAl[o];
                #pragma unroll
                for (int j2 = 0; j2 < 4; j2++) {
                    MMAF16(acc[i2][j2], ah, bh[j2]);
                    MMAF16(acc[i2][j2], ah, bl[j2]);
                    MMAF16(acc[i2][j2], al, bh[j2]);
                }
            }
        }
    }

    int g = lane >> 2, t = lane & 3;
    float* C = scores + (long)b * SEQ * SEQ;
    #pragma unroll
    for (int i2 = 0; i2 < 4; i2++) {
        int gm = m0 + (wm * 4 + i2) * 16 + g;
        #pragma unroll
        for (int j2 = 0; j2 < 4; j2++) {
            int gn = n0 + (wn * 4 + j2) * 8 + t * 2;
            *(float2*)&C[(long)gm * SEQ + gn] = make_float2(acc[i2][j2][0], acc[i2][j2][1]);
            *(float2*)&C[(long)(gm + 8) * SEQ + gn] = make_float2(acc[i2][j2][2], acc[i2][j2][3]);
        }
    }
}

// ---------------- flash attention: V loaded directly from qkv; packed A-blob out ----------------
__global__ __launch_bounds__(256, 1)
void flash_kernel(const float* __restrict__ qkv, uint32_t* __restrict__ oblob, float scale) {
    __shared__ uint32_t sK[6144];
    __shared__ uint32_t sV[6144];
    int z = blockIdx.z, b = z >> 3, h = z & 7;
    int m0 = blockIdx.y * 128;
    int tid = threadIdx.x, lane = tid & 31, wid = tid >> 5;
    int t = lane & 3, g = lane >> 2;

    const float* Qg = qkv + ((long)b * 1024 + m0) * 2304 + h * 96;
    const float* Kg = qkv + (long)b * 1024 * 2304 + 768 + h * 96;
    const float* Vg = qkv + (long)b * 1024 * 2304 + 1536 + h * 96;

    #pragma unroll
    for (int i = 0; i < 12; i++) {
        int idx = tid + 256 * i;
        int r = idx / 24, q = idx % 24;
        int k0 = q * 4;
        int im = r >> 4, gg = r & 7, row8 = (r >> 3) & 1;
        int kg = k0 >> 4, k8 = (k0 >> 3) & 1, t0 = (k0 >> 1) & 3;
        int base = ((im * 6 + kg) * 32 + gg * 4 + t0) * 4 + row8 + 2 * k8;
        float4 v = *(const float4*)(Qg + (long)r * 2304 + k0);
        sK[base]     = pack_h2(v.x, v.y);
        sK[base + 4] = pack_h2(v.z, v.w);
    }
    __syncthreads();
    uint4 qf[6];
    #pragma unroll
    for (int kg = 0; kg < 6; kg++)
        qf[kg] = *(const uint4*)&sK[((wid * 6 + kg) * 32 + lane) * 4];
    __syncthreads();

    float mr0 = -1e30f, mr1 = -1e30f, l0 = 0.f, l1 = 0.f;
    float accO[12][4];
    #pragma unroll
    for (int j = 0; j < 12; j++)
        #pragma unroll
        for (int c = 0; c < 4; c++) accO[j][c] = 0.f;

    for (int kt = 0; kt < 8; kt++) {
        #pragma unroll
        for (int i = 0; i < 12; i++) {
            int idx = tid + 256 * i;
            int r = idx / 24, q = idx % 24;
            int k0 = q * 4;
            int jn = r >> 3, nn = r & 7;
            int kg = k0 >> 4, k8 = (k0 >> 3) & 1, t0 = (k0 >> 1) & 3;
            int base = ((jn * 6 + kg) * 32 + nn * 4 + t0) * 2 + k8;
            float4 v = *(const float4*)(Kg + (long)(kt * 128 + r) * 2304 + k0);
            sK[base]     = pack_h2(v.x, v.y);
            sK[base + 2] = pack_h2(v.z, v.w);
        }
        // V tile loaded directly from qkv: thread -> (d, token pair)
        #pragma unroll
        for (int i = 0; i < 24; i++) {
            int idx = tid + 256 * i;
            int d = idx % 96, tp = idx / 96;
            int ltok = tp * 2;
            long gtok = (long)(kt * 128 + ltok);
            float v0 = Vg[gtok * 2304 + d];
            float v1 = Vg[(gtok + 1) * 2304 + d];
            int jn = d >> 3, nn = d & 7;
            int kg = ltok >> 4, k8 = (ltok >> 3) & 1, t0 = (ltok >> 1) & 3;
            int base = ((jn * 8 + kg) * 32 + nn * 4 + t0) * 2 + k8;
            sV[base] = pack_h2(v0, v1);
        }
        __syncthreads();

        float accS[16][4];
        #pragma unroll
        for (int j = 0; j < 16; j++)
            #pragma unroll
            for (int c = 0; c < 4; c++) accS[j][c] = 0.f;
        #pragma unroll
        for (int kg = 0; kg < 6; kg++)
            #pragma unroll
            for (int jn = 0; jn < 16; jn++) {
                uint2 bf = *(const uint2*)&sK[((jn * 6 + kg) * 32 + lane) * 2];
                MMAF16(accS[jn], qf[kg], bf);
            }

        float mx0 = -1e30f, mx1 = -1e30f;
        #pragma unroll
        for (int jn = 0; jn < 16; jn++) {
            accS[jn][0] *= scale; accS[jn][1] *= scale;
            accS[jn][2] *= scale; accS[jn][3] *= scale;
            mx0 = fmaxf(mx0, fmaxf(accS[jn][0], accS[jn][1]));
            mx1 = fmaxf(mx1, fmaxf(accS[jn][2], accS[jn][3]));
        }
        mx0 = fmaxf(mx0, __shfl_xor_sync(0xffffffffu, mx0, 1));
        mx0 = fmaxf(mx0, __shfl_xor_sync(0xffffffffu, mx0, 2));
        mx1 = fmaxf(mx1, __shfl_xor_sync(0xffffffffu, mx1, 1));
        mx1 = fmaxf(mx1, __shfl_xor_sync(0xffffffffu, mx1, 2));

        float mn0 = fmaxf(mr0, mx0), mn1 = fmaxf(mr1, mx1);
        float cr0 = fexp(mr0 - mn0), cr1 = fexp(mr1 - mn1);

        float s0 = 0.f, s1 = 0.f;
        uint32_t plo[16], phi[16];
        #pragma unroll
        for (int jn = 0; jn < 16; jn++) {
            float e0 = fexp(accS[jn][0] - mn0);
            float e1 = fexp(accS[jn][1] - mn0);
            float e2 = fexp(accS[jn][2] - mn1);
            float e3 = fexp(accS[jn][3] - mn1);
            s0 += e0 + e1; s1 += e2 + e3;
            plo[jn] = pack_h2(e0, e1);
            phi[jn] = pack_h2(e2, e3);
        }
        s0 += __shfl_xor_sync(0xffffffffu, s0, 1);
        s0 += __shfl_xor_sync(0xffffffffu, s0, 2);
        s1 += __shfl_xor_sync(0xffffffffu, s1, 1);
        s1 += __shfl_xor_sync(0xffffffffu, s1, 2);

        l0 = l0 * cr0 + s0;
        l1 = l1 * cr1 + s1;
        mr0 = mn0; mr1 = mn1;
        #pragma unroll
        for (int j = 0; j < 12; j++) {
            accO[j][0] *= cr0; accO[j][1] *= cr0;
            accO[j][2] *= cr1; accO[j][3] *= cr1;
        }

        #pragma unroll
        for (int kg = 0; kg < 8; kg++) {
            uint4 af = make_uint4(plo[2 * kg], phi[2 * kg], plo[2 * kg + 1], phi[2 * kg + 1]);
            #pragma unroll
            for (int jn = 0; jn < 12; jn++) {
                uint2 bf = *(const uint2*)&sV[((jn * 8 + kg) * 32 + lane) * 2];
                MMAF16(accO[jn], af, bf);
            }
        }
        __syncthreads();
    }

    float inv0 = 1.f / l0, inv1 = 1.f / l1;
    long row0 = (long)(b * 1024 + m0 + wid * 16 + g);
    long mblk = row0 >> 7;
    #pragma unroll
    for (int jn = 0; jn < 12; jn++) {
        int kglob = h * 96 + jn * 8 + t * 2;
        int kch = kglob >> 5;
        int ikf = (jn >> 1) & 1, k8 = jn & 1;
        long word = ((mblk * 24 + kch) * 2048) + wid * 256 + ikf * 128 + lane * 4 + 2 * k8;
        uint2 pw;
        pw.x = pack_h2(accO[jn][0] * inv0, accO[jn][1] * inv0);
        pw.y = pack_h2(accO[jn][2] * inv1, accO[jn][3] * inv1);
        *(uint2*)&oblob[word] = pw;
    }
}

// ---------------- mma.sync fp16 GEMM + optional packed-A-blob emitter ----------------
__global__ __launch_bounds__(256, 2)
void mma_gemm(const uint32_t* __restrict__ Ap,
              const uint32_t* __restrict__ Wp,
              float* __restrict__ C0, long ldc0, const float* __restrict__ bias0, int nsplit,
              float* __restrict__ C1, long ldc1, const float* __restrict__ bias1,
              int nch,
              uint32_t* __restrict__ packBlob, int packNch, int packKchBase) {
    __shared__ uint32_t sA[2][2048];
    __shared__ uint32_t sB[2][2048];

    int tid = threadIdx.x, lane = tid & 31, wid = tid >> 5;
    int wm = wid & 1, wn = wid >> 1;

    const uint4* Ab = (const uint4*)(Ap + (long)blockIdx.y * nch * 2048);
    const uint4* Wb = (const uint4*)(Wp + (long)blockIdx.x * nch * 2048);

    float acc[4][4][4];
    #pragma unroll
    for (int i = 0; i < 4; i++)
        #pragma unroll
        for (int j = 0; j < 4; j++)
            #pragma unroll
            for (int c = 0; c < 4; c++) acc[i][j][c] = 0.f;

    uint4 va0 = Ab[tid], va1 = Ab[tid + 256];
    uint4 vb0 = Wb[tid], vb1 = Wb[tid + 256];
    ((uint4*)sA[0])[tid] = va0; ((uint4*)sA[0])[tid + 256] = va1;
    ((uint4*)sB[0])[tid] = vb0; ((uint4*)sB[0])[tid + 256] = vb1;
    __syncthreads();

    for (int it = 0; it < nch; it++) {
        int buf = it & 1;
        bool more = (it + 1 < nch);
        if (more) {
            const uint4* An = Ab + (long)(it + 1) * 512;
            const uint4* Wn = Wb + (long)(it + 1) * 512;
            va0 = An[tid]; va1 = An[tid + 256];
            vb0 = Wn[tid]; vb1 = Wn[tid + 256];
        }
        #pragma unroll
        for (int ikf = 0; ikf < 2; ikf++) {
            uint4 af[4];
            uint2 bf[4];
            #pragma unroll
            for (int i2 = 0; i2 < 4; i2++)
                af[i2] = *(const uint4*)&sA[buf][(((wm * 4 + i2) * 2 + ikf) * 32 + lane) * 4];
            #pragma unroll
            for (int j2 = 0; j2 < 4; j2++)
                bf[j2] = *(const uint2*)&sB[buf][(((wn * 4 + j2) * 2 + ikf) * 32 + lane) * 2];
            #pragma unroll
            for (int i2 = 0; i2 < 4; i2++)
                #pragma unroll
                for (int j2 = 0; j2 < 4; j2++)
                    MMAF16(acc[i2][j2], af[i2], bf[j2]);
        }
        __syncthreads();
        if (more) {
            int nb = buf ^ 1;
            ((uint4*)sA[nb])[tid] = va0; ((uint4*)sA[nb])[tid + 256] = va1;
            ((uint4*)sB[nb])[tid] = vb0; ((uint4*)sB[nb])[tid + 256] = vb1;
            __syncthreads();
        }
    }

    float* C; long ldc; const float* bias; int n0;
    if ((int)blockIdx.x < nsplit) {
        C = C0; ldc = ldc0; bias = bias0; n0 = blockIdx.x * 128;
    } else {
        C = C1; ldc = ldc1; bias = bias1; n0 = (blockIdx.x - nsplit) * 128;
    }
    int m0 = blockIdx.y * 128;
    int g = lane >> 2, t = lane & 3;
    #pragma unroll
    for (int i2 = 0; i2 < 4; i2++) {
        int im = wm * 4 + i2;
        int gm = m0 + im * 16 + g;
        #pragma unroll
        for (int j2 = 0; j2 < 4; j2++) {
            int gn = n0 + (wn * 4 + j2) * 8 + t * 2;
            float b0 = __ldg(bias + gn);
            float b1 = __ldg(bias + gn + 1);
            float2 v0, v1;
            v0.x = acc[i2][j2][0] + b0;
            v0.y = acc[i2][j2][1] + b1;
            v1.x = acc[i2][j2][2] + b0;
            v1.y = acc[i2][j2][3] + b1;
            *(float2*)&C[(long)gm * ldc + gn] = v0;
            *(float2*)&C[(long)(gm + 8) * ldc + gn] = v1;
            if (packBlob) {
                int kch = packKchBase + (n0 >> 5) + wn;
                long word = (((long)blockIdx.y * packNch + kch) * 2048)
                          + im * 256 + (j2 >> 1) * 128 + lane * 4 + 2 * (j2 & 1);
                uint2 pw;
                pw.x = pack_h2(v0.x, v0.y);
                pw.y = pack_h2(v1.x, v1.y);
                *(uint2*)&packBlob[word] = pw;
            }
        }
    }
}

// ---------------- misc ----------------
__global__ void zero_bytes_kernel(unsigned char* p, long n) {
    long i = (long)blockIdx.x * blockDim.x + threadIdx.x;
    long stride = (long)gridDim.x * blockDim.x;
    int* pi = (int*)p;
    long nw = n >> 2;
    for (; i < nw; i += stride) pi[i] = 0;
}

// ---------------- topk: warp-per-row single pass, jax tie-break ----------------
__global__ void topk_warp_kernel(const float* __restrict__ sim, int* __restrict__ idx_out) {
    long rowid = ((long)blockIdx.x * blockDim.x + threadIdx.x) >> 5;
    int lane = threadIdx.x & 31;
    if (rowid >= ROWS) return;
    const float* row = sim + rowid * SEQ;
    float v[5]; int id[5];
    #pragma unroll
    for (int i = 0; i < 5; i++) { v[i] = -INFINITY; id[i] = 0x7fffffff; }
    for (int t = lane; t < SEQ; t += 32) {
        float x = row[t];
        if (x > v[4] || (x == v[4] && t < id[4])) {
            v[4] = x; id[4] = t;
            #pragma unroll
            for (int j = 3; j >= 0; j--) {
                if (v[j + 1] > v[j] || (v[j + 1] == v[j] && id[j + 1] < id[j])) {
                    float tv = v[j]; v[j] = v[j + 1]; v[j + 1] = tv;
                    int ti = id[j]; id[j] = id[j + 1]; id[j + 1] = ti;
                }
            }
        }
    }
    #pragma unroll
    for (int sel = 0; sel < KNEIGH; sel++) {
        float bv = v[0]; int bi = id[0];
        #pragma unroll
        for (int o = 16; o > 0; o >>= 1) {
            float ov = __shfl_xor_sync(0xffffffffu, bv, o);
            int oi = __shfl_xor_sync(0xffffffffu, bi, o);
            if (ov > bv || (ov == bv && oi < bi)) { bv = ov; bi = oi; }
        }
        if (lane == 0) idx_out[rowid * KNEIGH + sel] = bi;
        if (bi == id[0]) {
            #pragma unroll
            for (int j = 0; j < 4; j++) { v[j] = v[j + 1]; id[j] = id[j + 1]; }
            v[4] = -INFINITY; id[4] = 0x7fffffff;
        }
    }
}

// ---------------- adjacency + degree ----------------
__global__ void scatter_adj_kernel(const int* __restrict__ idx, unsigned char* __restrict__ A) {
    int r = blockIdx.x * blockDim.x + threadIdx.x;
    if (r >= ROWS) return;
    int b = r >> 10, s = r & 1023;
    unsigned char* Ab = A + (long long)b * SEQ * SEQ;
    Ab[(long)s * SEQ + s] = 1;
    #pragma unroll
    for (int j = 0; j < KNEIGH; j++) {
        int t = idx[(long)r * KNEIGH + j];
        Ab[(long)s * SEQ + t] = 1;
        Ab[(long)t * SEQ + s] = 1;
    }
}
__global__ void degree_kernel(const unsigned char* __restrict__ A, float* __restrict__ dinv) {
    int r = blockIdx.x * blockDim.x + threadIdx.x;
    if (r >= ROWS) return;
    const uint32_t* row = (const uint32_t*)(A + (long long)r * SEQ);
    int d = 0;
    for (int i = 0; i < SEQ / 4; i++) {
        uint32_t w = row[i];
        d += (w & 0xff) + ((w >> 8) & 0xff) + ((w >> 16) & 0xff) + ((w >> 24) & 0xff);
    }
    dinv[r] = rsqrtf((float)d);
}

// ---------------- sparse GCN aggregate: cat fp32 + cat-blob (kch 0..23) ----------------
__global__ void gcn_agg_kernel(const unsigned char* __restrict__ A, const float* __restrict__ dinv,
                               const float* __restrict__ xw, const float* __restrict__ gcn_b,
                               float* __restrict__ cat, uint32_t* __restrict__ catblob) {
    int r = blockIdx.x;
    int b = r >> 10;
    const unsigned char* Arow = A + (long long)r * SEQ;
    __shared__ int   nbr[SEQ];
    __shared__ float wgt[SEQ];
    __shared__ float sbuf[DIM];
    __shared__ int cnt;
    int tid = threadIdx.x;
    if (tid == 0) cnt = 0;
    __syncthreads();
    for (int t = tid; t < SEQ; t += 256) {
        if (Arow[t]) {
            int p = atomicAdd(&cnt, 1);
            nbr[p] = t;
            wgt[p] = dinv[(b << 10) + t];
        }
    }
    __syncthreads();
    int n = cnt;
    float acc0 = 0.f, acc1 = 0.f, acc2 = 0.f;
    for (int i = 0; i < n; i++) {
        const float* row = xw + ((long)(b << 10) + nbr[i]) * DIM;
        float w = wgt[i];
        acc0 += w * row[tid];
        acc1 += w * row[tid + 256];
        acc2 += w * row[tid + 512];
    }
    float ws = dinv[r];
    long base = (long)r * (2 * DIM);
    float o0 = ws * acc0 + gcn_b[tid];
    float o1 = ws * acc1 + gcn_b[tid + 256];
    float o2 = ws * acc2 + gcn_b[tid + 512];
    cat[base + tid]       = o0;
    cat[base + tid + 256] = o1;
    cat[base + tid + 512] = o2;
    sbuf[tid] = o0; sbuf[tid + 256] = o1; sbuf[tid + 512] = o2;
    __syncthreads();
    long mblk = r >> 7;
    int rloc = r & 127;
    int im = rloc >> 4, row8 = (rloc >> 3) & 1, g = rloc & 7;
    for (int w = tid; w < 384; w += 256) {
        int kch = w >> 4, ikf = (w >> 3) & 1, k8 = (w >> 2) & 1, t = w & 3;
        long word = ((mblk * 48 + kch) * 2048) + im * 256 + ikf * 128
                  + (g * 4 + t) * 4 + 2 * k8 + row8;
        catblob[word] = pack_h2(sbuf[2 * w], sbuf[2 * w + 1]);
    }
}

// ---------------- gate + residual + layernorm: h fp32 + h-blob ----------------
__global__ void fuse_ln_kernel(const float* __restrict__ gatelin, const float* __restrict__ cat,
                               const float* __restrict__ hin, float* __restrict__ hout,
                               uint32_t* __restrict__ hblob,
                               const float* __restrict__ ln_scale, const float* __restrict__ ln_bias) {
    long r = blockIdx.x;
    int tid = threadIdx.x;
    __shared__ float red[256];
    __shared__ float sbuf[DIM];
    float f[3];
    #pragma unroll
    for (int i = 0; i < 3; i++) {
        int j = tid + 256 * i;
        float g  = gatelin[r * DIM + j];
        float gc = cat[r * (2 * DIM) + j];
        float at = cat[r * (2 * DIM) + DIM + j];
        float sg = 1.f / (1.f + fexp(-g));
        f[i] = sg * gc + (1.f - sg) * at + hin[r * DIM + j];
    }
    float s1 = f[0] + f[1] + f[2];
    red[tid] = s1; __syncthreads();
    #pragma unroll
    for (int o = 128; o > 0; o >>= 1) { if (tid < o) red[tid] += red[tid + o]; __syncthreads(); }
    float mu = red[0] * (1.f / DIM);
    __syncthreads();
    float s2 = 0.f;
    #pragma unroll
    for (int i = 0; i < 3; i++) { float d = f[i] - mu; s2 += d * d; }
    red[tid] = s2; __syncthreads();
    #pragma unroll
    for (int o = 128; o > 0; o >>= 1) { if (tid < o) red[tid] += red[tid + o]; __syncthreads(); }
    float var = red[0] * (1.f / DIM);
    float inv = rsqrtf(var + LN_EPS);
    #pragma unroll
    for (int i = 0; i < 3; i++) {
        int j = tid + 256 * i;
        float v = (f[i] - mu) * inv * ln_scale[j] + ln_bias[j];
        hout[r * DIM + j] = v;
        sbuf[j] = v;
    }
    __syncthreads();
    long mblk = r >> 7;
    int rloc = (int)(r & 127);
    int im = rloc >> 4, row8 = (rloc >> 3) & 1, g = rloc & 7;
    for (int w = tid; w < 384; w += 256) {
        int kch = w >> 4, ikf = (w >> 3) & 1, k8 = (w >> 2) & 1, t = w & 3;
        long word = ((mblk * 24 + kch) * 2048) + im * 256 + ikf * 128
                  + (g * 4 + t) * 4 + 2 * k8 + row8;
        hblob[word] = pack_h2(sbuf[2 * w], sbuf[2 * w + 1]);
    }
}

// ---------------- host helper ----------------
static void launch_mma(const uint32_t* Ap, const uint32_t* Wp, float* C, long ldc,
                       const float* bias, int M, int N, int K,
                       uint32_t* packBlob = nullptr, int packNch = 0, int packKchBase = 0) {
    dim3 grid(N / 128, M / 128, 1);
    mma_gemm<<<grid, 256>>>(Ap, Wp, C, ldc, bias, N / 128, C, ldc, bias, K / 32,
                            packBlob, packNch, packKchBase);
}

extern "C" void kernel_launch(void* const* d_in, const int* in_sizes, int n_in,
                              void* d_out, int out_size) {
    const float* x          = (const float*)d_in[0];
    const float* gcn_w      = (const float*)d_in[1];
    const float* gcn_b      = (const float*)d_in[2];
    const float* attn_in_w  = (const float*)d_in[3];
    const float* attn_in_b  = (const float*)d_in[4];
    const float* attn_out_w = (const float*)d_in[5];
    const float* attn_out_b = (const float*)d_in[6];
    const float* gate_w     = (const float*)d_in[7];
    const float* gate_b     = (const float*)d_in[8];
    const float* ln_scale   = (const float*)d_in[9];
    const float* ln_bias    = (const float*)d_in[10];
    const float* proj_w     = (const float*)d_in[11];
    const float* proj_b     = (const float*)d_in[12];
    float* out = (float*)d_out;

    static cudaStream_t s_side = nullptr;
    static cudaEvent_t ev_fork = nullptr;
    static cudaEvent_t ev_xw[NLAYERS], ev_agg[NLAYERS];
    if (!s_side) {
        cudaStreamCreateWithFlags(&s_side, cudaStreamNonBlocking);
        cudaEventCreateWithFlags(&ev_fork, cudaEventDisableTiming);
        for (int l = 0; l < NLAYERS; l++) {
            cudaEventCreateWithFlags(&ev_xw[l], cudaEventDisableTiming);
            cudaEventCreateWithFlags(&ev_agg[l], cudaEventDisableTiming);
        }
    }

    float *p_h, *p_xw, *p_qkv, *p_scores, *p_cat, *p_gate, *p_dinv;
    uint32_t *p_wp, *p_ap;
    unsigned char* p_adj;
    int* p_topk;
    cudaGetSymbolAddress((void**)&p_h, g_h);
    cudaGetSymbolAddress((void**)&p_xw, g_xw);
    cudaGetSymbolAddress((void**)&p_qkv, g_qkv);
    cudaGetSymbolAddress((void**)&p_scores, g_scores);
    cudaGetSymbolAddress((void**)&p_cat, g_cat);
    cudaGetSymbolAddress((void**)&p_gate, g_gate);
    cudaGetSymbolAddress((void**)&p_dinv, g_dinv);
    cudaGetSymbolAddress((void**)&p_adj, g_adj);
    cudaGetSymbolAddress((void**)&p_topk, g_topk);
    cudaGetSymbolAddress((void**)&p_wp, g_wp);
    cudaGetSymbolAddress((void**)&p_ap, g_ap);

    const float attn_scale = (float)(1.0 / sqrt((double)HDIM));

    // ---- fork: graph-construction chain on side stream ----
    cudaEventRecord(ev_fork, 0);
    cudaStreamWaitEvent(s_side, ev_fork, 0);
    sim_gemm<<<dim3(8, 8, BATCH), 256, 0, s_side>>>(x, p_scores);
    topk_warp_kernel<<<ROWS / 8, 256, 0, s_side>>>(p_scores, p_topk);
    zero_bytes_kernel<<<1024, 256, 0, s_side>>>(p_adj, (long long)BATCH * SEQ * SEQ);
    scatter_adj_kernel<<<(ROWS + 255) / 256, 256, 0, s_side>>>(p_topk, p_adj);
    degree_kernel<<<(ROWS + 255) / 256, 256, 0, s_side>>>(p_adj, p_dinv);

    // ---- main stream: batched weight pack (one launch) + x blob ----
    {
        PackTable tab;
        int ri = 0;
        long pref = 0;
        tab.pref[0] = 0;
        for (int l = 0; l < NLAYERS; l++) {
            tab.w[ri] = gcn_w + (long)l * DIM * DIM;        tab.wpOff[ri] = WP_FUSED(l);
            tab.N[ri] = DIM;     tab.K[ri] = DIM;
            pref += (long)DIM * DIM / 2;     tab.pref[++ri] = pref;
            tab.w[ri] = attn_in_w + (long)l * DIM * 3 * DIM; tab.wpOff[ri] = WP_FUSED(l) + 294912;
            tab.N[ri] = 3 * DIM; tab.K[ri] = DIM;
            pref += (long)DIM * 3 * DIM / 2; tab.pref[++ri] = pref;
            tab.w[ri] = attn_out_w + (long)l * DIM * DIM;   tab.wpOff[ri] = WP_AOW(l);
            tab.N[ri] = DIM;     tab.K[ri] = DIM;
            pref += (long)DIM * DIM / 2;     tab.pref[++ri] = pref;
            tab.w[ri] = gate_w + (long)l * 2 * DIM * DIM;   tab.wpOff[ri] = WP_GW(l);
            tab.N[ri] = DIM;     tab.K[ri] = 2 * DIM;
            pref += (long)2 * DIM * DIM / 2; tab.pref[++ri] = pref;
        }
        tab.w[ri] = proj_w; tab.wpOff[ri] = WP_PROJ;
        tab.N[ri] = DIM;    tab.K[ri] = DIM;
        pref += (long)DIM * DIM / 2; tab.pref[++ri] = pref;
        pack_all_weights<<<2048, 256>>>(tab);
    }
    pack_act_kernel<<<dim3(24, 64), 256>>>(x, p_ap + AP_H, DIM);

    for (int l = 0; l < NLAYERS; l++) {
        const float* gb  = gcn_b + (long)l * DIM;
        const float* aib = attn_in_b + (long)l * 3 * DIM;
        const float* aob = attn_out_b + (long)l * DIM;
        const float* gtb = gate_b + (long)l * DIM;
        const float* lns = ln_scale + (long)l * DIM;
        const float* lnb = ln_bias + (long)l * DIM;
        const float* hin = (l == 0) ? x : p_h;

        // fused: XW -> xw (n-blocks 0-5), QKV -> qkv (n-blocks 6-23); A = h blob
        {
            dim3 grid(24, ROWS / 128, 1);
            mma_gemm<<<grid, 256>>>(p_ap + AP_H, p_wp + WP_FUSED(l),
                                    p_xw, DIM, gb, 6,
                                    p_qkv, 3 * DIM, aib,
                                    24, nullptr, 0, 0);
        }
        cudaEventRecord(ev_xw[l], 0);

        // side stream: gcn_agg overlapped with attention path
        cudaStreamWaitEvent(s_side, ev_xw[l], 0);
        gcn_agg_kernel<<<ROWS, 256, 0, s_side>>>(p_adj, p_dinv, p_xw, gb, p_cat, p_ap + AP_CAT);
        cudaEventRecord(ev_agg[l], s_side);

        // main stream: flash attention (V direct from qkv)
        flash_kernel<<<dim3(1, 8, 64), 256>>>(p_qkv, p_ap + AP_O, attn_scale);
        // attn_out GEMM: cat fp32 [:,768:1536] + cat blob kch 24-47
        launch_mma(p_ap + AP_O, p_wp + WP_AOW(l), p_cat + DIM, 2 * DIM, aob,
                   ROWS, DIM, DIM, p_ap + AP_CAT, 48, 24);

        // join: gate GEMM needs both cat halves
        cudaStreamWaitEvent(0, ev_agg[l], 0);
        launch_mma(p_ap + AP_CAT, p_wp + WP_GW(l), p_gate, DIM, gtb, ROWS, DIM, 2 * DIM);
        // h = LN(gate*gcn + (1-gate)*attn + hin) -> h fp32 + h blob
        fuse_ln_kernel<<<ROWS, 256>>>(p_gate, p_cat, hin, p_h, p_ap + AP_H, lns, lnb);
    }

    // out = h @ proj_w + proj_b
    launch_mma(p_ap + AP_H, p_wp + WP_PROJ, out, DIM, proj_b, ROWS, DIM, DIM);
}

// round 15
// speedup vs baseline: 1.0552x; 1.0552x over previous
#include <cuda_runtime.h>
#include <math.h>
#include <stdint.h>

// ---------------- problem constants ----------------
#define BATCH 8
#define SEQ   1024
#define DIM   768
#define HEADS 8
#define HDIM  96
#define KNEIGH 5
#define NLAYERS 3
#define ROWS (BATCH*SEQ)  // 8192
#define LN_EPS 1e-5f

// ---------------- device scratch (static, allocation-free) ----------------
__device__ float g_h[ROWS * DIM];
__device__ float g_xw[ROWS * DIM];
__device__ float g_qkv[ROWS * 3 * DIM];
__device__ float g_scores[(long long)BATCH * SEQ * SEQ]; // sim workspace (32 MB)
__device__ float g_cat[ROWS * 2 * DIM];   // [gcn | attn] stride 1536 (fp32 for fuse_ln)
__device__ float g_gate[ROWS * DIM];
__device__ unsigned char g_adj[(long long)BATCH * SEQ * SEQ];    // 8 MB
__device__ float g_dinv[ROWS];
__device__ int   g_topk[ROWS * KNEIGH];
__device__ uint32_t g_wp[6488064];         // fp16 fragment-packed weights (26 MB)
__device__ uint32_t g_ap[12582912];        // fp16 fragment-packed activations (50 MB)
__device__ float g_vt[ROWS * DIM];         // V transposed per (b,h): [64, 96, 1024]

// A-blob regions inside g_ap (words)
#define AP_H   0L
#define AP_O   3145728L
#define AP_CAT 6291456L

// packed weight word offsets
#define WP_FUSED(l) ((long)(l) * 1179648)
#define WP_AOW(l)   (3538944L + (long)(l) * 294912L)
#define WP_GW(l)    (4423680L + (long)(l) * 589824L)
#define WP_PROJ     (6193152L)

__device__ __forceinline__ uint32_t pack_h2(float a, float b) {
    uint32_t r;
    asm("cvt.rn.f16x2.f32 %0, %2, %1;" : "=r"(r) : "f"(a), "f"(b));
    return r;
}
__device__ __forceinline__ float h2f_lo(uint32_t h) {
    float f;
    asm("{.reg .b16 lo, hi;\n\t"
        "mov.b32 {lo, hi}, %1;\n\t"
        "cvt.f32.f16 %0, lo;}" : "=f"(f) : "r"(h));
    return f;
}
__device__ __forceinline__ float h2f_hi(uint32_t h) {
    float f;
    asm("{.reg .b16 lo, hi;\n\t"
        "mov.b32 {lo, hi}, %1;\n\t"
        "cvt.f32.f16 %0, hi;}" : "=f"(f) : "r"(h));
    return f;
}

// FMA-only exp (no MUFU)
__device__ __forceinline__ float fexp(float x) {
    x = fmaxf(x, -87.0f);
    float y = x * 1.4426950408889634f;
    int i = __float2int_rn(y);
    float r = (y - (float)i) * 0.6931471805599453f;
    float p = 1.9841270e-4f;
    p = fmaf(p, r, 1.3888889e-3f);
    p = fmaf(p, r, 8.3333333e-3f);
    p = fmaf(p, r, 4.1666667e-2f);
    p = fmaf(p, r, 1.6666667e-1f);
    p = fmaf(p, r, 0.5f);
    p = fmaf(p, r, 1.0f);
    p = fmaf(p, r, 1.0f);
    return p * __int_as_float((i + 127) << 23);
}

#define MMAF16(d, a, b) \
    asm volatile("mma.sync.aligned.m16n8k16.row.col.f32.f16.f16.f32 " \
        "{%0,%1,%2,%3}, {%4,%5,%6,%7}, {%8,%9}, {%0,%1,%2,%3};" \
        : "+f"((d)[0]), "+f"((d)[1]), "+f"((d)[2]), "+f"((d)[3]) \
        : "r"((a).x), "r"((a).y), "r"((a).z), "r"((a).w), \
          "r"((b).x), "r"((b).y))

// ---------------- weight packing: w [K,N] fp32 -> fragment-packed fp16 (B-layout) ----------------
__global__ void pack_weights_kernel(const float* __restrict__ w, uint32_t* __restrict__ wp,
                                    int N, int K) {
    int nch = K >> 5;
    long total = (long)N * (K >> 1);
    for (long tId = (long)blockIdx.x * blockDim.x + threadIdx.x; tId < total;
         tId += (long)gridDim.x * blockDim.x) {
        int n = (int)(tId % N);
        int kp = (int)(tId / N);
        int k = kp * 2;
        float v0 = w[(long)k * N + n];
        float v1 = w[(long)(k + 1) * N + n];
        long blk = (long)(n >> 7) * nch + (k >> 5);
        int nloc = n & 127, kloc = k & 31;
        int widx = ((((nloc >> 3) * 2 + ((kloc >> 4) & 1)) * 32
                     + (nloc & 7) * 4 + ((kloc >> 1) & 3)) * 2) + ((kloc >> 3) & 1);
        wp[blk * 2048 + widx] = pack_h2(v0, v1);
    }
}

// ---------------- activation packing (x at layer 0 only) ----------------
__global__ void pack_act_kernel(const float* __restrict__ act, uint32_t* __restrict__ blob,
                                int K) {
    int kch = blockIdx.x, mblk = blockIdx.y;
    int nch = gridDim.x;
    const float* a0 = act + (long)mblk * 128 * K + kch * 32;
    uint32_t* out = blob + ((long)mblk * nch + kch) * 2048;
    int tid = threadIdx.x;
    #pragma unroll
    for (int i = 0; i < 8; i++) {
        int w = tid + 256 * i;
        int c = w & 3, lanep = (w >> 2) & 31, ikf = (w >> 7) & 1, im = w >> 8;
        int r = im * 16 + (c & 1) * 8 + (lanep >> 2);
        int k = ikf * 16 + ((c >> 1) & 1) * 8 + (lanep & 3) * 2;
        float2 v = *(const float2*)(a0 + (long)r * K + k);
        out[w] = pack_h2(v.x, v.y);
    }
}

// ---------------- sim = x x^T via fp16 hi/lo split (verified R9) ----------------
__global__ __launch_bounds__(256, 2)
void sim_gemm(const float* __restrict__ x, float* __restrict__ scores) {
    __shared__ uint32_t sAh[2048], sAl[2048], sBh[2048], sBl[2048];
    int b = blockIdx.z;
    int m0 = blockIdx.y * 128, n0 = blockIdx.x * 128;
    int tid = threadIdx.x, lane = tid & 31, wid = tid >> 5;
    int wm = wid & 1, wn = wid >> 1;
    const float* Xm = x + (long)b * SEQ * DIM + (long)m0 * DIM;
    const float* Xn = x + (long)b * SEQ * DIM + (long)n0 * DIM;

    int aR[4], aQ[4], aBase[4];
    #pragma unroll
    for (int i = 0; i < 4; i++) {
        int idx = tid + 256 * i;
        int r = idx >> 3, q = idx & 7;
        aR[i] = r; aQ[i] = q;
        int im = r >> 4, g = r & 7, row8 = (r >> 3) & 1;
        int ikf = q >> 2, k8 = (q >> 1) & 1;
        aBase[i] = ((im * 2 + ikf) * 32 + g * 4) * 4 + k8 * 2 + row8 + 8 * (q & 1);
    }
    int bR[4], bQ[4], bBase[4];
    #pragma unroll
    for (int i = 0; i < 4; i++) {
        int idx = tid + 256 * i;
        int r = idx >> 3, q = idx & 7;
        bR[i] = r; bQ[i] = q;
        int in = r >> 3, nn = r & 7;
        int ikf = q >> 2, k8 = (q >> 1) & 1;
        bBase[i] = ((in * 2 + ikf) * 32 + nn * 4) * 2 + k8 + 4 * (q & 1);
    }

    float acc[4][4][4];
    #pragma unroll
    for (int i = 0; i < 4; i++)
        #pragma unroll
        for (int j = 0; j < 4; j++)
            #pragma unroll
            for (int c = 0; c < 4; c++) acc[i][j][c] = 0.f;

    for (int it = 0; it < DIM / 32; it++) {
        long koff = (long)it * 32;
        float4 va[4], vb[4];
        #pragma unroll
        for (int i = 0; i < 4; i++)
            va[i] = *(const float4*)(Xm + (long)aR[i] * DIM + koff + aQ[i] * 4);
        #pragma unroll
        for (int i = 0; i < 4; i++)
            vb[i] = *(const float4*)(Xn + (long)bR[i] * DIM + koff + bQ[i] * 4);
        __syncthreads();
        #pragma unroll
        for (int i = 0; i < 4; i++) {
            uint32_t h0 = pack_h2(va[i].x, va[i].y);
            uint32_t h1 = pack_h2(va[i].z, va[i].w);
            uint32_t l0 = pack_h2(va[i].x - h2f_lo(h0), va[i].y - h2f_hi(h0));
            uint32_t l1 = pack_h2(va[i].z - h2f_lo(h1), va[i].w - h2f_hi(h1));
            sAh[aBase[i]] = h0; sAh[aBase[i] + 4] = h1;
            sAl[aBase[i]] = l0; sAl[aBase[i] + 4] = l1;
        }
        #pragma unroll
        for (int i = 0; i < 4; i++) {
            uint32_t h0 = pack_h2(vb[i].x, vb[i].y);
            uint32_t h1 = pack_h2(vb[i].z, vb[i].w);
            uint32_t l0 = pack_h2(vb[i].x - h2f_lo(h0), vb[i].y - h2f_hi(h0));
            uint32_t l1 = pack_h2(vb[i].z - h2f_lo(h1), vb[i].w - h2f_hi(h1));
            sBh[bBase[i]] = h0; sBh[bBase[i] + 2] = h1;
            sBl[bBase[i]] = l0; sBl[bBase[i] + 2] = l1;
        }
        __syncthreads();
        #pragma unroll
        for (int ikf = 0; ikf < 2; ikf++) {
            uint2 bh[4], bl[4];
            #pragma unroll
            for (int j2 = 0; j2 < 4; j2++) {
                int o = (((wn * 4 + j2) * 2 + ikf) * 32 + lane) * 2;
                bh[j2] = *(const uint2*)&sBh[o];
                bl[j2] = *(const uint2*)&sBl[o];
            }
            #pragma unroll
            for (int i2 = 0; i2 < 4; i2++) {
                int o = (((wm * 4 + i2) * 2 + ikf) * 32 + lane) * 4;
                uint4 ah = *(const uint4*)&sAh[o];
                uint4 al = *(const uint4*)&sAl[o];
                #pragma unroll
                for (int j2 = 0; j2 < 4; j2++) {
                    MMAF16(acc[i2][j2], ah, bh[j2]);
                    MMAF16(acc[i2][j2], ah, bl[j2]);
                    MMAF16(acc[i2][j2], al, bh[j2]);
                }
            }
        }
    }

    int g = lane >> 2, t = lane & 3;
    float* C = scores + (long)b * SEQ * SEQ;
    #pragma unroll
    for (int i2 = 0; i2 < 4; i2++) {
        int gm = m0 + (wm * 4 + i2) * 16 + g;
        #pragma unroll
        for (int j2 = 0; j2 < 4; j2++) {
            int gn = n0 + (wn * 4 + j2) * 8 + t * 2;
            *(float2*)&C[(long)gm * SEQ + gn] = make_float2(acc[i2][j2][0], acc[i2][j2][1]);
            *(float2*)&C[(long)(gm + 8) * SEQ + gn] = make_float2(acc[i2][j2][2], acc[i2][j2][3]);
        }
    }
}

// ---------------- flash attention: vt-based (verified R6), packed A-blob out ----------------
__global__ __launch_bounds__(256, 1)
void flash_kernel(const float* __restrict__ qkv, const float* __restrict__ vt,
                  uint32_t* __restrict__ oblob, float scale) {
    __shared__ uint32_t sK[6144];
    __shared__ uint32_t sV[6144];
    int z = blockIdx.z, b = z >> 3, h = z & 7;
    int m0 = blockIdx.y * 128;
    int tid = threadIdx.x, lane = tid & 31, wid = tid >> 5;
    int t = lane & 3, g = lane >> 2;

    const float* Qg = qkv + ((long)b * 1024 + m0) * 2304 + h * 96;
    const float* Kg = qkv + (long)b * 1024 * 2304 + 768 + h * 96;
    const float* Vg = vt + (long)z * 96 * 1024;

    #pragma unroll
    for (int i = 0; i < 12; i++) {
        int idx = tid + 256 * i;
        int r = idx / 24, q = idx % 24;
        int k0 = q * 4;
        int im = r >> 4, gg = r & 7, row8 = (r >> 3) & 1;
        int kg = k0 >> 4, k8 = (k0 >> 3) & 1, t0 = (k0 >> 1) & 3;
        int base = ((im * 6 + kg) * 32 + gg * 4 + t0) * 4 + row8 + 2 * k8;
        float4 v = *(const float4*)(Qg + (long)r * 2304 + k0);
        sK[base]     = pack_h2(v.x, v.y);
        sK[base + 4] = pack_h2(v.z, v.w);
    }
    __syncthreads();
    uint4 qf[6];
    #pragma unroll
    for (int kg = 0; kg < 6; kg++)
        qf[kg] = *(const uint4*)&sK[((wid * 6 + kg) * 32 + lane) * 4];
    __syncthreads();

    float mr0 = -1e30f, mr1 = -1e30f, l0 = 0.f, l1 = 0.f;
    float accO[12][4];
    #pragma unroll
    for (int j = 0; j < 12; j++)
        #pragma unroll
        for (int c = 0; c < 4; c++) accO[j][c] = 0.f;

    for (int kt = 0; kt < 8; kt++) {
        #pragma unroll
        for (int i = 0; i < 12; i++) {
            int idx = tid + 256 * i;
            int r = idx / 24, q = idx % 24;
            int k0 = q * 4;
            int jn = r >> 3, nn = r & 7;
            int kg = k0 >> 4, k8 = (k0 >> 3) & 1, t0 = (k0 >> 1) & 3;
            int base = ((jn * 6 + kg) * 32 + nn * 4 + t0) * 2 + k8;
            float4 v = *(const float4*)(Kg + (long)(kt * 128 + r) * 2304 + k0);
            sK[base]     = pack_h2(v.x, v.y);
            sK[base + 2] = pack_h2(v.z, v.w);
        }
        #pragma unroll
        for (int i = 0; i < 12; i++) {
            int idx = tid + 256 * i;
            int r = idx >> 5, q = idx & 31;
            int k0 = q * 4;
            int jn = r >> 3, nn = r & 7;
            int kg = k0 >> 4, k8 = (k0 >> 3) & 1, t0 = (k0 >> 1) & 3;
            int base = ((jn * 8 + kg) * 32 + nn * 4 + t0) * 2 + k8;
            float4 v = *(const float4*)(Vg + (long)r * 1024 + kt * 128 + k0);
            sV[base]     = pack_h2(v.x, v.y);
            sV[base + 2] = pack_h2(v.z, v.w);
        }
        __syncthreads();

        float accS[16][4];
        #pragma unroll
        for (int j = 0; j < 16; j++)
            #pragma unroll
            for (int c = 0; c < 4; c++) accS[j][c] = 0.f;
        #pragma unroll
        for (int kg = 0; kg < 6; kg++)
            #pragma unroll
            for (int jn = 0; jn < 16; jn++) {
                uint2 bf = *(const uint2*)&sK[((jn * 6 + kg) * 32 + lane) * 2];
                MMAF16(accS[jn], qf[kg], bf);
            }

        float mx0 = -1e30f, mx1 = -1e30f;
        #pragma unroll
        for (int jn = 0; jn < 16; jn++) {
            accS[jn][0] *= scale; accS[jn][1] *= scale;
            accS[jn][2] *= scale; accS[jn][3] *= scale;
            mx0 = fmaxf(mx0, fmaxf(accS[jn][0], accS[jn][1]));
            mx1 = fmaxf(mx1, fmaxf(accS[jn][2], accS[jn][3]));
        }
        mx0 = fmaxf(mx0, __shfl_xor_sync(0xffffffffu, mx0, 1));
        mx0 = fmaxf(mx0, __shfl_xor_sync(0xffffffffu, mx0, 2));
        mx1 = fmaxf(mx1, __shfl_xor_sync(0xffffffffu, mx1, 1));
        mx1 = fmaxf(mx1, __shfl_xor_sync(0xffffffffu, mx1, 2));

        float mn0 = fmaxf(mr0, mx0), mn1 = fmaxf(mr1, mx1);
        float cr0 = fexp(mr0 - mn0), cr1 = fexp(mr1 - mn1);

        float s0 = 0.f, s1 = 0.f;
        uint32_t plo[16], phi[16];
        #pragma unroll
        for (int jn = 0; jn < 16; jn++) {
            float e0 = fexp(accS[jn][0] - mn0);
            float e1 = fexp(accS[jn][1] - mn0);
            float e2 = fexp(accS[jn][2] - mn1);
            float e3 = fexp(accS[jn][3] - mn1);
            s0 += e0 + e1; s1 += e2 + e3;
            plo[jn] = pack_h2(e0, e1);
            phi[jn] = pack_h2(e2, e3);
        }
        s0 += __shfl_xor_sync(0xffffffffu, s0, 1);
        s0 += __shfl_xor_sync(0xffffffffu, s0, 2);
        s1 += __shfl_xor_sync(0xffffffffu, s1, 1);
        s1 += __shfl_xor_sync(0xffffffffu, s1, 2);

        l0 = l0 * cr0 + s0;
        l1 = l1 * cr1 + s1;
        mr0 = mn0; mr1 = mn1;
        #pragma unroll
        for (int j = 0; j < 12; j++) {
            accO[j][0] *= cr0; accO[j][1] *= cr0;
            accO[j][2] *= cr1; accO[j][3] *= cr1;
        }

        #pragma unroll
        for (int kg = 0; kg < 8; kg++) {
            uint4 af = make_uint4(plo[2 * kg], phi[2 * kg], plo[2 * kg + 1], phi[2 * kg + 1]);
            #pragma unroll
            for (int jn = 0; jn < 12; jn++) {
                uint2 bf = *(const uint2*)&sV[((jn * 8 + kg) * 32 + lane) * 2];
                MMAF16(accO[jn], af, bf);
            }
        }
        __syncthreads();
    }

    float inv0 = 1.f / l0, inv1 = 1.f / l1;
    long row0 = (long)(b * 1024 + m0 + wid * 16 + g);
    long mblk = row0 >> 7;
    #pragma unroll
    for (int jn = 0; jn < 12; jn++) {
        int kglob = h * 96 + jn * 8 + t * 2;
        int kch = kglob >> 5;
        int ikf = (jn >> 1) & 1, k8 = jn & 1;
        long word = ((mblk * 24 + kch) * 2048) + wid * 256 + ikf * 128 + lane * 4 + 2 * k8;
        uint2 pw;
        pw.x = pack_h2(accO[jn][0] * inv0, accO[jn][1] * inv0);
        pw.y = pack_h2(accO[jn][2] * inv1, accO[jn][3] * inv1);
        *(uint2*)&oblob[word] = pw;
    }
}

// ---------------- mma.sync fp16 GEMM + optional packed-A-blob emitter ----------------
__global__ __launch_bounds__(256, 2)
void mma_gemm(const uint32_t* __restrict__ Ap,
              const uint32_t* __restrict__ Wp,
              float* __restrict__ C0, long ldc0, const float* __restrict__ bias0, int nsplit,
              float* __restrict__ C1, long ldc1, const float* __restrict__ bias1,
              int nch,
              uint32_t* __restrict__ packBlob, int packNch, int packKchBase) {
    __shared__ uint32_t sA[2][2048];
    __shared__ uint32_t sB[2][2048];

    int tid = threadIdx.x, lane = tid & 31, wid = tid >> 5;
    int wm = wid & 1, wn = wid >> 1;

    const uint4* Ab = (const uint4*)(Ap + (long)blockIdx.y * nch * 2048);
    const uint4* Wb = (const uint4*)(Wp + (long)blockIdx.x * nch * 2048);

    float acc[4][4][4];
    #pragma unroll
    for (int i = 0; i < 4; i++)
        #pragma unroll
        for (int j = 0; j < 4; j++)
            #pragma unroll
            for (int c = 0; c < 4; c++) acc[i][j][c] = 0.f;

    uint4 va0 = Ab[tid], va1 = Ab[tid + 256];
    uint4 vb0 = Wb[tid], vb1 = Wb[tid + 256];
    ((uint4*)sA[0])[tid] = va0; ((uint4*)sA[0])[tid + 256] = va1;
    ((uint4*)sB[0])[tid] = vb0; ((uint4*)sB[0])[tid + 256] = vb1;
    __syncthreads();

    for (int it = 0; it < nch; it++) {
        int buf = it & 1;
        bool more = (it + 1 < nch);
        if (more) {
            const uint4* An = Ab + (long)(it + 1) * 512;
            const uint4* Wn = Wb + (long)(it + 1) * 512;
            va0 = An[tid]; va1 = An[tid + 256];
            vb0 = Wn[tid]; vb1 = Wn[tid + 256];
        }
        #pragma unroll
        for (int ikf = 0; ikf < 2; ikf++) {
            uint4 af[4];
            uint2 bf[4];
            #pragma unroll
            for (int i2 = 0; i2 < 4; i2++)
                af[i2] = *(const uint4*)&sA[buf][(((wm * 4 + i2) * 2 + ikf) * 32 + lane) * 4];
            #pragma unroll
            for (int j2 = 0; j2 < 4; j2++)
                bf[j2] = *(const uint2*)&sB[buf][(((wn * 4 + j2) * 2 + ikf) * 32 + lane) * 2];
            #pragma unroll
            for (int i2 = 0; i2 < 4; i2++)
                #pragma unroll
                for (int j2 = 0; j2 < 4; j2++)
                    MMAF16(acc[i2][j2], af[i2], bf[j2]);
        }
        __syncthreads();
        if (more) {
            int nb = buf ^ 1;
            ((uint4*)sA[nb])[tid] = va0; ((uint4*)sA[nb])[tid + 256] = va1;
            ((uint4*)sB[nb])[tid] = vb0; ((uint4*)sB[nb])[tid + 256] = vb1;
            __syncthreads();
        }
    }

    float* C; long ldc; const float* bias; int n0;
    if ((int)blockIdx.x < nsplit) {
        C = C0; ldc = ldc0; bias = bias0; n0 = blockIdx.x * 128;
    } else {
        C = C1; ldc = ldc1; bias = bias1; n0 = (blockIdx.x - nsplit) * 128;
    }
    int m0 = blockIdx.y * 128;
    int g = lane >> 2, t = lane & 3;
    #pragma unroll
    for (int i2 = 0; i2 < 4; i2++) {
        int im = wm * 4 + i2;
        int gm = m0 + im * 16 + g;
        #pragma unroll
        for (int j2 = 0; j2 < 4; j2++) {
            int gn = n0 + (wn * 4 + j2) * 8 + t * 2;
            float b0 = __ldg(bias + gn);
            float b1 = __ldg(bias + gn + 1);
            float2 v0, v1;
            v0.x = acc[i2][j2][0] + b0;
            v0.y = acc[i2][j2][1] + b1;
            v1.x = acc[i2][j2][2] + b0;
            v1.y = acc[i2][j2][3] + b1;
            *(float2*)&C[(long)gm * ldc + gn] = v0;
            *(float2*)&C[(long)(gm + 8) * ldc + gn] = v1;
            if (packBlob) {
                int kch = packKchBase + (n0 >> 5) + wn;
                long word = (((long)blockIdx.y * packNch + kch) * 2048)
                          + im * 256 + (j2 >> 1) * 128 + lane * 4 + 2 * (j2 & 1);
                uint2 pw;
                pw.x = pack_h2(v0.x, v0.y);
                pw.y = pack_h2(v1.x, v1.y);
                *(uint2*)&packBlob[word] = pw;
            }
        }
    }
}

// ---------------- V transpose for flash ----------------
__global__ void transpose_v_kernel(const float* __restrict__ qkv, float* __restrict__ vt) {
    int z = blockIdx.z; int b = z >> 3, h = z & 7;
    __shared__ float tb[32][33];
    int d0 = blockIdx.x * 32, t0 = blockIdx.y * 32;
    int tx = threadIdx.x, ty = threadIdx.y;
    const float* src = qkv + (long)b * 1024 * 2304 + 1536 + h * 96;
    for (int i = ty; i < 32; i += 8)
        tb[i][tx] = src[(long)(t0 + i) * 2304 + d0 + tx];
    __syncthreads();
    float* dst = vt + ((long)z * 96 + d0) * 1024 + t0;
    for (int j = ty; j < 32; j += 8)
        dst[(long)j * 1024 + tx] = tb[tx][j];
}

// ---------------- misc ----------------
__global__ void zero_bytes_kernel(unsigned char* p, long n) {
    long i = (long)blockIdx.x * blockDim.x + threadIdx.x;
    long stride = (long)gridDim.x * blockDim.x;
    int* pi = (int*)p;
    long nw = n >> 2;
    for (; i < nw; i += stride) pi[i] = 0;
}

// ---------------- topk: warp-per-row single pass, jax tie-break ----------------
__global__ void topk_warp_kernel(const float* __restrict__ sim, int* __restrict__ idx_out) {
    long rowid = ((long)blockIdx.x * blockDim.x + threadIdx.x) >> 5;
    int lane = threadIdx.x & 31;
    if (rowid >= ROWS) return;
    const float* row = sim + rowid * SEQ;
    float v[5]; int id[5];
    #pragma unroll
    for (int i = 0; i < 5; i++) { v[i] = -INFINITY; id[i] = 0x7fffffff; }
    for (int t = lane; t < SEQ; t += 32) {
        float x = row[t];
        if (x > v[4] || (x == v[4] && t < id[4])) {
            v[4] = x; id[4] = t;
            #pragma unroll
            for (int j = 3; j >= 0; j--) {
                if (v[j + 1] > v[j] || (v[j + 1] == v[j] && id[j + 1] < id[j])) {
                    float tv = v[j]; v[j] = v[j + 1]; v[j + 1] = tv;
                    int ti = id[j]; id[j] = id[j + 1]; id[j + 1] = ti;
                }
            }
        }
    }
    #pragma unroll
    for (int sel = 0; sel < KNEIGH; sel++) {
        float bv = v[0]; int bi = id[0];
        #pragma unroll
        for (int o = 16; o > 0; o >>= 1) {
            float ov = __shfl_xor_sync(0xffffffffu, bv, o);
            int oi = __shfl_xor_sync(0xffffffffu, bi, o);
            if (ov > bv || (ov == bv && oi < bi)) { bv = ov; bi = oi; }
        }
        if (lane == 0) idx_out[rowid * KNEIGH + sel] = bi;
        if (bi == id[0]) {
            #pragma unroll
            for (int j = 0; j < 4; j++) { v[j] = v[j + 1]; id[j] = id[j + 1]; }
            v[4] = -INFINITY; id[4] = 0x7fffffff;
        }
    }
}

// ---------------- adjacency + degree ----------------
__global__ void scatter_adj_kernel(const int* __restrict__ idx, unsigned char* __restrict__ A) {
    int r = blockIdx.x * blockDim.x + threadIdx.x;
    if (r >= ROWS) return;
    int b = r >> 10, s = r & 1023;
    unsigned char* Ab = A + (long long)b * SEQ * SEQ;
    Ab[(long)s * SEQ + s] = 1;
    #pragma unroll
    for (int j = 0; j < KNEIGH; j++) {
        int t = idx[(long)r * KNEIGH + j];
        Ab[(long)s * SEQ + t] = 1;
        Ab[(long)t * SEQ + s] = 1;
    }
}
__global__ void degree_kernel(const unsigned char* __restrict__ A, float* __restrict__ dinv) {
    int r = blockIdx.x * blockDim.x + threadIdx.x;
    if (r >= ROWS) return;
    const uint32_t* row = (const uint32_t*)(A + (long long)r * SEQ);
    int d = 0;
    for (int i = 0; i < SEQ / 4; i++) {
        uint32_t w = row[i];
        d += (w & 0xff) + ((w >> 8) & 0xff) + ((w >> 16) & 0xff) + ((w >> 24) & 0xff);
    }
    dinv[r] = rsqrtf((float)d);
}

// ---------------- sparse GCN aggregate: cat fp32 + cat-blob (kch 0..23) ----------------
__global__ void gcn_agg_kernel(const unsigned char* __restrict__ A, const float* __restrict__ dinv,
                               const float* __restrict__ xw, const float* __restrict__ gcn_b,
                               float* __restrict__ cat, uint32_t* __restrict__ catblob) {
    int r = blockIdx.x;
    int b = r >> 10;
    const unsigned char* Arow = A + (long long)r * SEQ;
    __shared__ int   nbr[SEQ];
    __shared__ float wgt[SEQ];
    __shared__ float sbuf[DIM];
    __shared__ int cnt;
    int tid = threadIdx.x;
    if (tid == 0) cnt = 0;
    __syncthreads();
    for (int t = tid; t < SEQ; t += 256) {
        if (Arow[t]) {
            int p = atomicAdd(&cnt, 1);
            nbr[p] = t;
            wgt[p] = dinv[(b << 10) + t];
        }
    }
    __syncthreads();
    int n = cnt;
    float acc0 = 0.f, acc1 = 0.f, acc2 = 0.f;
    for (int i = 0; i < n; i++) {
        const float* row = xw + ((long)(b << 10) + nbr[i]) * DIM;
        float w = wgt[i];
        acc0 += w * row[tid];
        acc1 += w * row[tid + 256];
        acc2 += w * row[tid + 512];
    }
    float ws = dinv[r];
    long base = (long)r * (2 * DIM);
    float o0 = ws * acc0 + gcn_b[tid];
    float o1 = ws * acc1 + gcn_b[tid + 256];
    float o2 = ws * acc2 + gcn_b[tid + 512];
    cat[base + tid]       = o0;
    cat[base + tid + 256] = o1;
    cat[base + tid + 512] = o2;
    sbuf[tid] = o0; sbuf[tid + 256] = o1; sbuf[tid + 512] = o2;
    __syncthreads();
    long mblk = r >> 7;
    int rloc = r & 127;
    int im = rloc >> 4, row8 = (rloc >> 3) & 1, g = rloc & 7;
    for (int w = tid; w < 384; w += 256) {
        int kch = w >> 4, ikf = (w >> 3) & 1, k8 = (w >> 2) & 1, t = w & 3;
        long word = ((mblk * 48 + kch) * 2048) + im * 256 + ikf * 128
                  + (g * 4 + t) * 4 + 2 * k8 + row8;
        catblob[word] = pack_h2(sbuf[2 * w], sbuf[2 * w + 1]);
    }
}

// ---------------- gate + residual + layernorm: h fp32 + h-blob ----------------
__global__ void fuse_ln_kernel(const float* __restrict__ gatelin, const float* __restrict__ cat,
                               const float* __restrict__ hin, float* __restrict__ hout,
                               uint32_t* __restrict__ hblob,
                               const float* __restrict__ ln_scale, const float* __restrict__ ln_bias) {
    long r = blockIdx.x;
    int tid = threadIdx.x;
    __shared__ float red[256];
    __shared__ float sbuf[DIM];
    float f[3];
    #pragma unroll
    for (int i = 0; i < 3; i++) {
        int j = tid + 256 * i;
        float g  = gatelin[r * DIM + j];
        float gc = cat[r * (2 * DIM) + j];
        float at = cat[r * (2 * DIM) + DIM + j];
        float sg = 1.f / (1.f + fexp(-g));
        f[i] = sg * gc + (1.f - sg) * at + hin[r * DIM + j];
    }
    float s1 = f[0] + f[1] + f[2];
    red[tid] = s1; __syncthreads();
    #pragma unroll
    for (int o = 128; o > 0; o >>= 1) { if (tid < o) red[tid] += red[tid + o]; __syncthreads(); }
    float mu = red[0] * (1.f / DIM);
    __syncthreads();
    float s2 = 0.f;
    #pragma unroll
    for (int i = 0; i < 3; i++) { float d = f[i] - mu; s2 += d * d; }
    red[tid] = s2; __syncthreads();
    #pragma unroll
    for (int o = 128; o > 0; o >>= 1) { if (tid < o) red[tid] += red[tid + o]; __syncthreads(); }
    float var = red[0] * (1.f / DIM);
    float inv = rsqrtf(var + LN_EPS);
    #pragma unroll
    for (int i = 0; i < 3; i++) {
        int j = tid + 256 * i;
        float v = (f[i] - mu) * inv * ln_scale[j] + ln_bias[j];
        hout[r * DIM + j] = v;
        sbuf[j] = v;
    }
    __syncthreads();
    long mblk = r >> 7;
    int rloc = (int)(r & 127);
    int im = rloc >> 4, row8 = (rloc >> 3) & 1, g = rloc & 7;
    for (int w = tid; w < 384; w += 256) {
        int kch = w >> 4, ikf = (w >> 3) & 1, k8 = (w >> 2) & 1, t = w & 3;
        long word = ((mblk * 24 + kch) * 2048) + im * 256 + ikf * 128
                  + (g * 4 + t) * 4 + 2 * k8 + row8;
        hblob[word] = pack_h2(sbuf[2 * w], sbuf[2 * w + 1]);
    }
}

// ---------------- host helper ----------------
static void launch_mma(const uint32_t* Ap, const uint32_t* Wp, float* C, long ldc,
                       const float* bias, int M, int N, int K,
                       uint32_t* packBlob = nullptr, int packNch = 0, int packKchBase = 0) {
    dim3 grid(N / 128, M / 128, 1);
    mma_gemm<<<grid, 256>>>(Ap, Wp, C, ldc, bias, N / 128, C, ldc, bias, K / 32,
                            packBlob, packNch, packKchBase);
}

extern "C" void kernel_launch(void* const* d_in, const int* in_sizes, int n_in,
                              void* d_out, int out_size) {
    const float* x          = (const float*)d_in[0];
    const float* gcn_w      = (const float*)d_in[1];
    const float* gcn_b      = (const float*)d_in[2];
    const float* attn_in_w  = (const float*)d_in[3];
    const float* attn_in_b  = (const float*)d_in[4];
    const float* attn_out_w = (const float*)d_in[5];
    const float* attn_out_b = (const float*)d_in[6];
    const float* gate_w     = (const float*)d_in[7];
    const float* gate_b     = (const float*)d_in[8];
    const float* ln_scale   = (const float*)d_in[9];
    const float* ln_bias    = (const float*)d_in[10];
    const float* proj_w     = (const float*)d_in[11];
    const float* proj_b     = (const float*)d_in[12];
    float* out = (float*)d_out;

    static cudaStream_t s_side = nullptr, s_w = nullptr;
    static cudaEvent_t ev_fork = nullptr, ev_wpack = nullptr;
    static cudaEvent_t ev_xw[NLAYERS], ev_agg[NLAYERS];
    if (!s_side) {
        cudaStreamCreateWithFlags(&s_side, cudaStreamNonBlocking);
        cudaStreamCreateWithFlags(&s_w, cudaStreamNonBlocking);
        cudaEventCreateWithFlags(&ev_fork, cudaEventDisableTiming);
        cudaEventCreateWithFlags(&ev_wpack, cudaEventDisableTiming);
        for (int l = 0; l < NLAYERS; l++) {
            cudaEventCreateWithFlags(&ev_xw[l], cudaEventDisableTiming);
            cudaEventCreateWithFlags(&ev_agg[l], cudaEventDisableTiming);
        }
    }

    float *p_h, *p_xw, *p_qkv, *p_scores, *p_cat, *p_gate, *p_dinv, *p_vt;
    uint32_t *p_wp, *p_ap;
    unsigned char* p_adj;
    int* p_topk;
    cudaGetSymbolAddress((void**)&p_h, g_h);
    cudaGetSymbolAddress((void**)&p_xw, g_xw);
    cudaGetSymbolAddress((void**)&p_qkv, g_qkv);
    cudaGetSymbolAddress((void**)&p_scores, g_scores);
    cudaGetSymbolAddress((void**)&p_cat, g_cat);
    cudaGetSymbolAddress((void**)&p_gate, g_gate);
    cudaGetSymbolAddress((void**)&p_dinv, g_dinv);
    cudaGetSymbolAddress((void**)&p_adj, g_adj);
    cudaGetSymbolAddress((void**)&p_topk, g_topk);
    cudaGetSymbolAddress((void**)&p_wp, g_wp);
    cudaGetSymbolAddress((void**)&p_ap, g_ap);
    cudaGetSymbolAddress((void**)&p_vt, g_vt);

    const float attn_scale = (float)(1.0 / sqrt((double)HDIM));
    dim3 tb(32, 8);

    // ---- fork: graph-construction chain on side stream ----
    cudaEventRecord(ev_fork, 0);
    cudaStreamWaitEvent(s_side, ev_fork, 0);
    sim_gemm<<<dim3(8, 8, BATCH), 256, 0, s_side>>>(x, p_scores);
    topk_warp_kernel<<<ROWS / 8, 256, 0, s_side>>>(p_scores, p_topk);
    zero_bytes_kernel<<<1024, 256, 0, s_side>>>(p_adj, (long long)BATCH * SEQ * SEQ);
    scatter_adj_kernel<<<(ROWS + 255) / 256, 256, 0, s_side>>>(p_topk, p_adj);
    degree_kernel<<<(ROWS + 255) / 256, 256, 0, s_side>>>(p_adj, p_dinv);

    // ---- weight-pack stream: everything not needed by the first fused GEMM ----
    cudaStreamWaitEvent(s_w, ev_fork, 0);
    for (int l = 1; l < NLAYERS; l++) {
        pack_weights_kernel<<<512, 256, 0, s_w>>>(gcn_w + (long)l * DIM * DIM, p_wp + WP_FUSED(l), DIM, DIM);
        pack_weights_kernel<<<512, 256, 0, s_w>>>(attn_in_w + (long)l * DIM * 3 * DIM,
                                                  p_wp + WP_FUSED(l) + 294912, 3 * DIM, DIM);
    }
    for (int l = 0; l < NLAYERS; l++) {
        pack_weights_kernel<<<512, 256, 0, s_w>>>(attn_out_w + (long)l * DIM * DIM, p_wp + WP_AOW(l), DIM, DIM);
        pack_weights_kernel<<<512, 256, 0, s_w>>>(gate_w + (long)l * 2 * DIM * DIM, p_wp + WP_GW(l), DIM, 2 * DIM);
    }
    pack_weights_kernel<<<512, 256, 0, s_w>>>(proj_w, p_wp + WP_PROJ, DIM, DIM);
    cudaEventRecord(ev_wpack, s_w);

    // ---- main stream: only layer-0 fused packs + x blob (gates the first GEMM) ----
    pack_weights_kernel<<<512, 256>>>(gcn_w, p_wp + WP_FUSED(0), DIM, DIM);
    pack_weights_kernel<<<512, 256>>>(attn_in_w, p_wp + WP_FUSED(0) + 294912, 3 * DIM, DIM);
    pack_act_kernel<<<dim3(24, 64), 256>>>(x, p_ap + AP_H, DIM);

    bool wjoined = false;
    for (int l = 0; l < NLAYERS; l++) {
        const float* gb  = gcn_b + (long)l * DIM;
        const float* aib = attn_in_b + (long)l * 3 * DIM;
        const float* aob = attn_out_b + (long)l * DIM;
        const float* gtb = gate_b + (long)l * DIM;
        const float* lns = ln_scale + (long)l * DIM;
        const float* lnb = ln_bias + (long)l * DIM;
        const float* hin = (l == 0) ? x : p_h;

        // fused: XW -> xw (n-blocks 0-5), QKV -> qkv (n-blocks 6-23); A = h blob
        {
            dim3 grid(24, ROWS / 128, 1);
            mma_gemm<<<grid, 256>>>(p_ap + AP_H, p_wp + WP_FUSED(l),
                                    p_xw, DIM, gb, 6,
                                    p_qkv, 3 * DIM, aib,
                                    24, nullptr, 0, 0);
        }
        cudaEventRecord(ev_xw[l], 0);

        // side stream: gcn_agg overlapped with attention path
        cudaStreamWaitEvent(s_side, ev_xw[l], 0);
        gcn_agg_kernel<<<ROWS, 256, 0, s_side>>>(p_adj, p_dinv, p_xw, gb, p_cat, p_ap + AP_CAT);
        cudaEventRecord(ev_agg[l], s_side);

        // main stream: attention path
        transpose_v_kernel<<<dim3(3, 32, 64), tb>>>(p_qkv, p_vt);
        flash_kernel<<<dim3(1, 8, 64), 256>>>(p_qkv, p_vt, p_ap + AP_O, attn_scale);
        // join weight-pack stream before first use of AOW/GW/proj/fused(1,2)
        if (!wjoined) { cudaStreamWaitEvent(0, ev_wpack, 0); wjoined = true; }
        // attn_out GEMM: cat fp32 [:,768:1536] + cat blob kch 24-47
        launch_mma(p_ap + AP_O, p_wp + WP_AOW(l), p_cat + DIM, 2 * DIM, aob,
                   ROWS, DIM, DIM, p_ap + AP_CAT, 48, 24);

        // join: gate GEMM needs both cat halves
        cudaStreamWaitEvent(0, ev_agg[l], 0);
        launch_mma(p_ap + AP_CAT, p_wp + WP_GW(l), p_gate, DIM, gtb, ROWS, DIM, 2 * DIM);
        // h = LN(gate*gcn + (1-gate)*attn + hin) -> h fp32 + h blob
        fuse_ln_kernel<<<ROWS, 256>>>(p_gate, p_cat, hin, p_h, p_ap + AP_H, lns, lnb);
    }

    // out = h @ proj_w + proj_b
    launch_mma(p_ap + AP_H, p_wp + WP_PROJ, out, DIM, proj_b, ROWS, DIM, DIM);
}

// round 16
// speedup vs baseline: 1.0790x; 1.0226x over previous
#include <cuda_runtime.h>
#include <math.h>
#include <stdint.h>

// ---------------- problem constants ----------------
#define BATCH 8
#define SEQ   1024
#define DIM   768
#define HEADS 8
#define HDIM  96
#define KNEIGH 5
#define NLAYERS 3
#define ROWS (BATCH*SEQ)  // 8192
#define LN_EPS 1e-5f

// ---------------- device scratch (static, allocation-free) ----------------
__device__ float g_h[ROWS * DIM];
__device__ float g_xw[ROWS * DIM];
__device__ float g_qkv[ROWS * 3 * DIM];
__device__ float g_scores[(long long)BATCH * SEQ * SEQ]; // sim workspace (32 MB)
__device__ float g_cat[ROWS * 2 * DIM];   // [gcn | attn] stride 1536 (fp32 for fuse_ln)
__device__ float g_gate[ROWS * DIM];
__device__ unsigned char g_adj[(long long)BATCH * SEQ * SEQ];    // 8 MB
__device__ float g_dinv[ROWS];
__device__ int   g_topk[ROWS * KNEIGH];
__device__ uint32_t g_wp[6488064];         // fp16 fragment-packed weights (26 MB)
__device__ uint32_t g_ap[12582912];        // fp16 fragment-packed activations (50 MB)
__device__ float g_vt[ROWS * DIM];         // V transposed per (b,h): [64, 96, 1024]

// A-blob regions inside g_ap (words)
#define AP_H   0L
#define AP_O   3145728L
#define AP_CAT 6291456L

// packed weight word offsets
#define WP_FUSED(l) ((long)(l) * 1179648)
#define WP_AOW(l)   (3538944L + (long)(l) * 294912L)
#define WP_GW(l)    (4423680L + (long)(l) * 589824L)
#define WP_PROJ     (6193152L)

__device__ __forceinline__ uint32_t pack_h2(float a, float b) {
    uint32_t r;
    asm("cvt.rn.f16x2.f32 %0, %2, %1;" : "=r"(r) : "f"(a), "f"(b));
    return r;
}
__device__ __forceinline__ float h2f_lo(uint32_t h) {
    float f;
    asm("{.reg .b16 lo, hi;\n\t"
        "mov.b32 {lo, hi}, %1;\n\t"
        "cvt.f32.f16 %0, lo;}" : "=f"(f) : "r"(h));
    return f;
}
__device__ __forceinline__ float h2f_hi(uint32_t h) {
    float f;
    asm("{.reg .b16 lo, hi;\n\t"
        "mov.b32 {lo, hi}, %1;\n\t"
        "cvt.f32.f16 %0, hi;}" : "=f"(f) : "r"(h));
    return f;
}

// FMA-only exp (no MUFU)
__device__ __forceinline__ float fexp(float x) {
    x = fmaxf(x, -87.0f);
    float y = x * 1.4426950408889634f;
    int i = __float2int_rn(y);
    float r = (y - (float)i) * 0.6931471805599453f;
    float p = 1.9841270e-4f;
    p = fmaf(p, r, 1.3888889e-3f);
    p = fmaf(p, r, 8.3333333e-3f);
    p = fmaf(p, r, 4.1666667e-2f);
    p = fmaf(p, r, 1.6666667e-1f);
    p = fmaf(p, r, 0.5f);
    p = fmaf(p, r, 1.0f);
    p = fmaf(p, r, 1.0f);
    return p * __int_as_float((i + 127) << 23);
}

#define MMAF16(d, a, b) \
    asm volatile("mma.sync.aligned.m16n8k16.row.col.f32.f16.f16.f32 " \
        "{%0,%1,%2,%3}, {%4,%5,%6,%7}, {%8,%9}, {%0,%1,%2,%3};" \
        : "+f"((d)[0]), "+f"((d)[1]), "+f"((d)[2]), "+f"((d)[3]) \
        : "r"((a).x), "r"((a).y), "r"((a).z), "r"((a).w), \
          "r"((b).x), "r"((b).y))

// ---------------- weight packing: w [K,N] fp32 -> fragment-packed fp16 (B-layout) ----------------
__global__ void pack_weights_kernel(const float* __restrict__ w, uint32_t* __restrict__ wp,
                                    int N, int K) {
    int nch = K >> 5;
    long total = (long)N * (K >> 1);
    for (long tId = (long)blockIdx.x * blockDim.x + threadIdx.x; tId < total;
         tId += (long)gridDim.x * blockDim.x) {
        int n = (int)(tId % N);
        int kp = (int)(tId / N);
        int k = kp * 2;
        float v0 = w[(long)k * N + n];
        float v1 = w[(long)(k + 1) * N + n];
        long blk = (long)(n >> 7) * nch + (k >> 5);
        int nloc = n & 127, kloc = k & 31;
        int widx = ((((nloc >> 3) * 2 + ((kloc >> 4) & 1)) * 32
                     + (nloc & 7) * 4 + ((kloc >> 1) & 3)) * 2) + ((kloc >> 3) & 1);
        wp[blk * 2048 + widx] = pack_h2(v0, v1);
    }
}

// ---------------- activation packing (x at layer 0 only) ----------------
__global__ void pack_act_kernel(const float* __restrict__ act, uint32_t* __restrict__ blob,
                                int K) {
    int kch = blockIdx.x, mblk = blockIdx.y;
    int nch = gridDim.x;
    const float* a0 = act + (long)mblk * 128 * K + kch * 32;
    uint32_t* out = blob + ((long)mblk * nch + kch) * 2048;
    int tid = threadIdx.x;
    #pragma unroll
    for (int i = 0; i < 8; i++) {
        int w = tid + 256 * i;
        int c = w & 3, lanep = (w >> 2) & 31, ikf = (w >> 7) & 1, im = w >> 8;
        int r = im * 16 + (c & 1) * 8 + (lanep >> 2);
        int k = ikf * 16 + ((c >> 1) & 1) * 8 + (lanep & 3) * 2;
        float2 v = *(const float2*)(a0 + (long)r * K + k);
        out[w] = pack_h2(v.x, v.y);
    }
}

// ---------------- sim = x x^T via fp16 hi/lo split (verified R9) ----------------
__global__ __launch_bounds__(256, 2)
void sim_gemm(const float* __restrict__ x, float* __restrict__ scores) {
    __shared__ uint32_t sAh[2048], sAl[2048], sBh[2048], sBl[2048];
    int b = blockIdx.z;
    int m0 = blockIdx.y * 128, n0 = blockIdx.x * 128;
    int tid = threadIdx.x, lane = tid & 31, wid = tid >> 5;
    int wm = wid & 1, wn = wid >> 1;
    const float* Xm = x + (long)b * SEQ * DIM + (long)m0 * DIM;
    const float* Xn = x + (long)b * SEQ * DIM + (long)n0 * DIM;

    int aR[4], aQ[4], aBase[4];
    #pragma unroll
    for (int i = 0; i < 4; i++) {
        int idx = tid + 256 * i;
        int r = idx >> 3, q = idx & 7;
        aR[i] = r; aQ[i] = q;
        int im = r >> 4, g = r & 7, row8 = (r >> 3) & 1;
        int ikf = q >> 2, k8 = (q >> 1) & 1;
        aBase[i] = ((im * 2 + ikf) * 32 + g * 4) * 4 + k8 * 2 + row8 + 8 * (q & 1);
    }
    int bR[4], bQ[4], bBase[4];
    #pragma unroll
    for (int i = 0; i < 4; i++) {
        int idx = tid + 256 * i;
        int r = idx >> 3, q = idx & 7;
        bR[i] = r; bQ[i] = q;
        int in = r >> 3, nn = r & 7;
        int ikf = q >> 2, k8 = (q >> 1) & 1;
        bBase[i] = ((in * 2 + ikf) * 32 + nn * 4) * 2 + k8 + 4 * (q & 1);
    }

    float acc[4][4][4];
    #pragma unroll
    for (int i = 0; i < 4; i++)
        #pragma unroll
        for (int j = 0; j < 4; j++)
            #pragma unroll
            for (int c = 0; c < 4; c++) acc[i][j][c] = 0.f;

    for (int it = 0; it < DIM / 32; it++) {
        long koff = (long)it * 32;
        float4 va[4], vb[4];
        #pragma unroll
        for (int i = 0; i < 4; i++)
            va[i] = *(const float4*)(Xm + (long)aR[i] * DIM + koff + aQ[i] * 4);
        #pragma unroll
        for (int i = 0; i < 4; i++)
            vb[i] = *(const float4*)(Xn + (long)bR[i] * DIM + koff + bQ[i] * 4);
        __syncthreads();
        #pragma unroll
        for (int i = 0; i < 4; i++) {
            uint32_t h0 = pack_h2(va[i].x, va[i].y);
            uint32_t h1 = pack_h2(va[i].z, va[i].w);
            uint32_t l0 = pack_h2(va[i].x - h2f_lo(h0), va[i].y - h2f_hi(h0));
            uint32_t l1 = pack_h2(va[i].z - h2f_lo(h1), va[i].w - h2f_hi(h1));
            sAh[aBase[i]] = h0; sAh[aBase[i] + 4] = h1;
            sAl[aBase[i]] = l0; sAl[aBase[i] + 4] = l1;
        }
        #pragma unroll
        for (int i = 0; i < 4; i++) {
            uint32_t h0 = pack_h2(vb[i].x, vb[i].y);
            uint32_t h1 = pack_h2(vb[i].z, vb[i].w);
            uint32_t l0 = pack_h2(vb[i].x - h2f_lo(h0), vb[i].y - h2f_hi(h0));
            uint32_t l1 = pack_h2(vb[i].z - h2f_lo(h1), vb[i].w - h2f_hi(h1));
            sBh[bBase[i]] = h0; sBh[bBase[i] + 2] = h1;
            sBl[bBase[i]] = l0; sBl[bBase[i] + 2] = l1;
        }
        __syncthreads();
        #pragma unroll
        for (int ikf = 0; ikf < 2; ikf++) {
            uint2 bh[4], bl[4];
            #pragma unroll
            for (int j2 = 0; j2 < 4; j2++) {
                int o = (((wn * 4 + j2) * 2 + ikf) * 32 + lane) * 2;
                bh[j2] = *(const uint2*)&sBh[o];
                bl[j2] = *(const uint2*)&sBl[o];
            }
            #pragma unroll
            for (int i2 = 0; i2 < 4; i2++) {
                int o = (((wm * 4 + i2) * 2 + ikf) * 32 + lane) * 4;
                uint4 ah = *(const uint4*)&sAh[o];
                uint4 al = *(const uint4*)&sAl[o];
                #pragma unroll
                for (int j2 = 0; j2 < 4; j2++) {
                    MMAF16(acc[i2][j2], ah, bh[j2]);
                    MMAF16(acc[i2][j2], ah, bl[j2]);
                    MMAF16(acc[i2][j2], al, bh[j2]);
                }
            }
        }
    }

    int g = lane >> 2, t = lane & 3;
    float* C = scores + (long)b * SEQ * SEQ;
    #pragma unroll
    for (int i2 = 0; i2 < 4; i2++) {
        int gm = m0 + (wm * 4 + i2) * 16 + g;
        #pragma unroll
        for (int j2 = 0; j2 < 4; j2++) {
            int gn = n0 + (wn * 4 + j2) * 8 + t * 2;
            *(float2*)&C[(long)gm * SEQ + gn] = make_float2(acc[i2][j2][0], acc[i2][j2][1]);
            *(float2*)&C[(long)(gm + 8) * SEQ + gn] = make_float2(acc[i2][j2][2], acc[i2][j2][3]);
        }
    }
}

// ---------------- flash attention: vt-based (verified R6), packed A-blob out ----------------
__global__ __launch_bounds__(256, 1)
void flash_kernel(const float* __restrict__ qkv, const float* __restrict__ vt,
                  uint32_t* __restrict__ oblob, float scale) {
    __shared__ uint32_t sK[6144];
    __shared__ uint32_t sV[6144];
    int z = blockIdx.z, b = z >> 3, h = z & 7;
    int m0 = blockIdx.y * 128;
    int tid = threadIdx.x, lane = tid & 31, wid = tid >> 5;
    int t = lane & 3, g = lane >> 2;

    const float* Qg = qkv + ((long)b * 1024 + m0) * 2304 + h * 96;
    const float* Kg = qkv + (long)b * 1024 * 2304 + 768 + h * 96;
    const float* Vg = vt + (long)z * 96 * 1024;

    #pragma unroll
    for (int i = 0; i < 12; i++) {
        int idx = tid + 256 * i;
        int r = idx / 24, q = idx % 24;
        int k0 = q * 4;
        int im = r >> 4, gg = r & 7, row8 = (r >> 3) & 1;
        int kg = k0 >> 4, k8 = (k0 >> 3) & 1, t0 = (k0 >> 1) & 3;
        int base = ((im * 6 + kg) * 32 + gg * 4 + t0) * 4 + row8 + 2 * k8;
        float4 v = *(const float4*)(Qg + (long)r * 2304 + k0);
        sK[base]     = pack_h2(v.x, v.y);
        sK[base + 4] = pack_h2(v.z, v.w);
    }
    __syncthreads();
    uint4 qf[6];
    #pragma unroll
    for (int kg = 0; kg < 6; kg++)
        qf[kg] = *(const uint4*)&sK[((wid * 6 + kg) * 32 + lane) * 4];
    __syncthreads();

    float mr0 = -1e30f, mr1 = -1e30f, l0 = 0.f, l1 = 0.f;
    float accO[12][4];
    #pragma unroll
    for (int j = 0; j < 12; j++)
        #pragma unroll
        for (int c = 0; c < 4; c++) accO[j][c] = 0.f;

    for (int kt = 0; kt < 8; kt++) {
        #pragma unroll
        for (int i = 0; i < 12; i++) {
            int idx = tid + 256 * i;
            int r = idx / 24, q = idx % 24;
            int k0 = q * 4;
            int jn = r >> 3, nn = r & 7;
            int kg = k0 >> 4, k8 = (k0 >> 3) & 1, t0 = (k0 >> 1) & 3;
            int base = ((jn * 6 + kg) * 32 + nn * 4 + t0) * 2 + k8;
            float4 v = *(const float4*)(Kg + (long)(kt * 128 + r) * 2304 + k0);
            sK[base]     = pack_h2(v.x, v.y);
            sK[base + 2] = pack_h2(v.z, v.w);
        }
        #pragma unroll
        for (int i = 0; i < 12; i++) {
            int idx = tid + 256 * i;
            int r = idx >> 5, q = idx & 31;
            int k0 = q * 4;
            int jn = r >> 3, nn = r & 7;
            int kg = k0 >> 4, k8 = (k0 >> 3) & 1, t0 = (k0 >> 1) & 3;
            int base = ((jn * 8 + kg) * 32 + nn * 4 + t0) * 2 + k8;
            float4 v = *(const float4*)(Vg + (long)r * 1024 + kt * 128 + k0);
            sV[base]     = pack_h2(v.x, v.y);
            sV[base + 2] = pack_h2(v.z, v.w);
        }
        __syncthreads();

        float accS[16][4];
        #pragma unroll
        for (int j = 0; j < 16; j++)
            #pragma unroll
            for (int c = 0; c < 4; c++) accS[j][c] = 0.f;
        #pragma unroll
        for (int kg = 0; kg < 6; kg++)
            #pragma unroll
            for (int jn = 0; jn < 16; jn++) {
                uint2 bf = *(const uint2*)&sK[((jn * 6 + kg) * 32 + lane) * 2];
                MMAF16(accS[jn], qf[kg], bf);
            }

        float mx0 = -1e30f, mx1 = -1e30f;
        #pragma unroll
        for (int jn = 0; jn < 16; jn++) {
            accS[jn][0] *= scale; accS[jn][1] *= scale;
            accS[jn][2] *= scale; accS[jn][3] *= scale;
            mx0 = fmaxf(mx0, fmaxf(accS[jn][0], accS[jn][1]));
            mx1 = fmaxf(mx1, fmaxf(accS[jn][2], accS[jn][3]));
        }
        mx0 = fmaxf(mx0, __shfl_xor_sync(0xffffffffu, mx0, 1));
        mx0 = fmaxf(mx0, __shfl_xor_sync(0xffffffffu, mx0, 2));
        mx1 = fmaxf(mx1, __shfl_xor_sync(0xffffffffu, mx1, 1));
        mx1 = fmaxf(mx1, __shfl_xor_sync(0xffffffffu, mx1, 2));

        float mn0 = fmaxf(mr0, mx0), mn1 = fmaxf(mr1, mx1);
        float cr0 = fexp(mr0 - mn0), cr1 = fexp(mr1 - mn1);

        float s0 = 0.f, s1 = 0.f;
        uint32_t plo[16], phi[16];
        #pragma unroll
        for (int jn = 0; jn < 16; jn++) {
            float e0 = fexp(accS[jn][0] - mn0);
            float e1 = fexp(accS[jn][1] - mn0);
            float e2 = fexp(accS[jn][2] - mn1);
            float e3 = fexp(accS[jn][3] - mn1);
            s0 += e0 + e1; s1 += e2 + e3;
            plo[jn] = pack_h2(e0, e1);
            phi[jn] = pack_h2(e2, e3);
        }
        s0 += __shfl_xor_sync(0xffffffffu, s0, 1);
        s0 += __shfl_xor_sync(0xffffffffu, s0, 2);
        s1 += __shfl_xor_sync(0xffffffffu, s1, 1);
        s1 += __shfl_xor_sync(0xffffffffu, s1, 2);

        l0 = l0 * cr0 + s0;
        l1 = l1 * cr1 + s1;
        mr0 = mn0; mr1 = mn1;
        #pragma unroll
        for (int j = 0; j < 12; j++) {
            accO[j][0] *= cr0; accO[j][1] *= cr0;
            accO[j][2] *= cr1; accO[j][3] *= cr1;
        }

        #pragma unroll
        for (int kg = 0; kg < 8; kg++) {
            uint4 af = make_uint4(plo[2 * kg], phi[2 * kg], plo[2 * kg + 1], phi[2 * kg + 1]);
            #pragma unroll
            for (int jn = 0; jn < 12; jn++) {
                uint2 bf = *(const uint2*)&sV[((jn * 8 + kg) * 32 + lane) * 2];
                MMAF16(accO[jn], af, bf);
            }
        }
        __syncthreads();
    }

    float inv0 = 1.f / l0, inv1 = 1.f / l1;
    long row0 = (long)(b * 1024 + m0 + wid * 16 + g);
    long mblk = row0 >> 7;
    #pragma unroll
    for (int jn = 0; jn < 12; jn++) {
        int kglob = h * 96 + jn * 8 + t * 2;
        int kch = kglob >> 5;
        int ikf = (jn >> 1) & 1, k8 = jn & 1;
        long word = ((mblk * 24 + kch) * 2048) + wid * 256 + ikf * 128 + lane * 4 + 2 * k8;
        uint2 pw;
        pw.x = pack_h2(accO[jn][0] * inv0, accO[jn][1] * inv0);
        pw.y = pack_h2(accO[jn][2] * inv1, accO[jn][3] * inv1);
        *(uint2*)&oblob[word] = pw;
    }
}

// ---------------- mma.sync fp16 GEMM + packed-A-blob emitter + vt emitter ----------------
__global__ __launch_bounds__(256, 2)
void mma_gemm(const uint32_t* __restrict__ Ap,
              const uint32_t* __restrict__ Wp,
              float* __restrict__ C0, long ldc0, const float* __restrict__ bias0, int nsplit,
              float* __restrict__ C1, long ldc1, const float* __restrict__ bias1,
              int nch,
              uint32_t* __restrict__ packBlob, int packNch, int packKchBase,
              float* __restrict__ vtOut) {
    __shared__ uint32_t sA[2][2048];
    __shared__ uint32_t sB[2][2048];

    int tid = threadIdx.x, lane = tid & 31, wid = tid >> 5;
    int wm = wid & 1, wn = wid >> 1;

    const uint4* Ab = (const uint4*)(Ap + (long)blockIdx.y * nch * 2048);
    const uint4* Wb = (const uint4*)(Wp + (long)blockIdx.x * nch * 2048);

    float acc[4][4][4];
    #pragma unroll
    for (int i = 0; i < 4; i++)
        #pragma unroll
        for (int j = 0; j < 4; j++)
            #pragma unroll
            for (int c = 0; c < 4; c++) acc[i][j][c] = 0.f;

    uint4 va0 = Ab[tid], va1 = Ab[tid + 256];
    uint4 vb0 = Wb[tid], vb1 = Wb[tid + 256];
    ((uint4*)sA[0])[tid] = va0; ((uint4*)sA[0])[tid + 256] = va1;
    ((uint4*)sB[0])[tid] = vb0; ((uint4*)sB[0])[tid + 256] = vb1;
    __syncthreads();

    for (int it = 0; it < nch; it++) {
        int buf = it & 1;
        bool more = (it + 1 < nch);
        if (more) {
            const uint4* An = Ab + (long)(it + 1) * 512;
            const uint4* Wn = Wb + (long)(it + 1) * 512;
            va0 = An[tid]; va1 = An[tid + 256];
            vb0 = Wn[tid]; vb1 = Wn[tid + 256];
        }
        #pragma unroll
        for (int ikf = 0; ikf < 2; ikf++) {
            uint4 af[4];
            uint2 bf[4];
            #pragma unroll
            for (int i2 = 0; i2 < 4; i2++)
                af[i2] = *(const uint4*)&sA[buf][(((wm * 4 + i2) * 2 + ikf) * 32 + lane) * 4];
            #pragma unroll
            for (int j2 = 0; j2 < 4; j2++)
                bf[j2] = *(const uint2*)&sB[buf][(((wn * 4 + j2) * 2 + ikf) * 32 + lane) * 2];
            #pragma unroll
            for (int i2 = 0; i2 < 4; i2++)
                #pragma unroll
                for (int j2 = 0; j2 < 4; j2++)
                    MMAF16(acc[i2][j2], af[i2], bf[j2]);
        }
        __syncthreads();
        if (more) {
            int nb = buf ^ 1;
            ((uint4*)sA[nb])[tid] = va0; ((uint4*)sA[nb])[tid + 256] = va1;
            ((uint4*)sB[nb])[tid] = vb0; ((uint4*)sB[nb])[tid + 256] = vb1;
            __syncthreads();
        }
    }

    float* C; long ldc; const float* bias; int n0;
    if ((int)blockIdx.x < nsplit) {
        C = C0; ldc = ldc0; bias = bias0; n0 = blockIdx.x * 128;
    } else {
        C = C1; ldc = ldc1; bias = bias1; n0 = (blockIdx.x - nsplit) * 128;
    }
    int m0 = blockIdx.y * 128;
    int g = lane >> 2, t = lane & 3;
    #pragma unroll
    for (int i2 = 0; i2 < 4; i2++) {
        int im = wm * 4 + i2;
        int gm = m0 + im * 16 + g;
        #pragma unroll
        for (int j2 = 0; j2 < 4; j2++) {
            int gn = n0 + (wn * 4 + j2) * 8 + t * 2;
            float b0 = __ldg(bias + gn);
            float b1 = __ldg(bias + gn + 1);
            float2 v0, v1;
            v0.x = acc[i2][j2][0] + b0;
            v0.y = acc[i2][j2][1] + b1;
            v1.x = acc[i2][j2][2] + b0;
            v1.y = acc[i2][j2][3] + b1;
            *(float2*)&C[(long)gm * ldc + gn] = v0;
            *(float2*)&C[(long)(gm + 8) * ldc + gn] = v1;
            if (packBlob) {
                int kch = packKchBase + (n0 >> 5) + wn;
                long word = (((long)blockIdx.y * packNch + kch) * 2048)
                          + im * 256 + (j2 >> 1) * 128 + lane * 4 + 2 * (j2 & 1);
                uint2 pw;
                pw.x = pack_h2(v0.x, v0.y);
                pw.y = pack_h2(v1.x, v1.y);
                *(uint2*)&packBlob[word] = pw;
            }
            if (vtOut) {
                int gnv = gn - 1536;
                if (gnv >= 0) {
                    int hh = gnv / 96, dd = gnv - hh * 96;
                    int bb = gm >> 10, tok = gm & 1023;
                    long base = (((long)(bb * 8 + hh) * 96 + dd) * 1024) + tok;
                    vtOut[base]         = v0.x;
                    vtOut[base + 1024]  = v0.y;
                    vtOut[base + 8]     = v1.x;
                    vtOut[base + 1032]  = v1.y;
                }
            }
        }
    }
}

// ---------------- misc ----------------
__global__ void zero_bytes_kernel(unsigned char* p, long n) {
    long i = (long)blockIdx.x * blockDim.x + threadIdx.x;
    long stride = (long)gridDim.x * blockDim.x;
    int* pi = (int*)p;
    long nw = n >> 2;
    for (; i < nw; i += stride) pi[i] = 0;
}

// ---------------- topk: warp-per-row single pass, jax tie-break ----------------
__global__ void topk_warp_kernel(const float* __restrict__ sim, int* __restrict__ idx_out) {
    long rowid = ((long)blockIdx.x * blockDim.x + threadIdx.x) >> 5;
    int lane = threadIdx.x & 31;
    if (rowid >= ROWS) return;
    const float* row = sim + rowid * SEQ;
    float v[5]; int id[5];
    #pragma unroll
    for (int i = 0; i < 5; i++) { v[i] = -INFINITY; id[i] = 0x7fffffff; }
    for (int t = lane; t < SEQ; t += 32) {
        float x = row[t];
        if (x > v[4] || (x == v[4] && t < id[4])) {
            v[4] = x; id[4] = t;
            #pragma unroll
            for (int j = 3; j >= 0; j--) {
                if (v[j + 1] > v[j] || (v[j + 1] == v[j] && id[j + 1] < id[j])) {
                    float tv = v[j]; v[j] = v[j + 1]; v[j + 1] = tv;
                    int ti = id[j]; id[j] = id[j + 1]; id[j + 1] = ti;
                }
            }
        }
    }
    #pragma unroll
    for (int sel = 0; sel < KNEIGH; sel++) {
        float bv = v[0]; int bi = id[0];
        #pragma unroll
        for (int o = 16; o > 0; o >>= 1) {
            float ov = __shfl_xor_sync(0xffffffffu, bv, o);
            int oi = __shfl_xor_sync(0xffffffffu, bi, o);
            if (ov > bv || (ov == bv && oi < bi)) { bv = ov; bi = oi; }
        }
        if (lane == 0) idx_out[rowid * KNEIGH + sel] = bi;
        if (bi == id[0]) {
            #pragma unroll
            for (int j = 0; j < 4; j++) { v[j] = v[j + 1]; id[j] = id[j + 1]; }
            v[4] = -INFINITY; id[4] = 0x7fffffff;
        }
    }
}

// ---------------- adjacency + degree ----------------
__global__ void scatter_adj_kernel(const int* __restrict__ idx, unsigned char* __restrict__ A) {
    int r = blockIdx.x * blockDim.x + threadIdx.x;
    if (r >= ROWS) return;
    int b = r >> 10, s = r & 1023;
    unsigned char* Ab = A + (long long)b * SEQ * SEQ;
    Ab[(long)s * SEQ + s] = 1;
    #pragma unroll
    for (int j = 0; j < KNEIGH; j++) {
        int t = idx[(long)r * KNEIGH + j];
        Ab[(long)s * SEQ + t] = 1;
        Ab[(long)t * SEQ + s] = 1;
    }
}
__global__ void degree_kernel(const unsigned char* __restrict__ A, float* __restrict__ dinv) {
    int r = blockIdx.x * blockDim.x + threadIdx.x;
    if (r >= ROWS) return;
    const uint32_t* row = (const uint32_t*)(A + (long long)r * SEQ);
    int d = 0;
    for (int i = 0; i < SEQ / 4; i++) {
        uint32_t w = row[i];
        d += (w & 0xff) + ((w >> 8) & 0xff) + ((w >> 16) & 0xff) + ((w >> 24) & 0xff);
    }
    dinv[r] = rsqrtf((float)d);
}

// ---------------- sparse GCN aggregate: cat fp32 + cat-blob (kch 0..23) ----------------
__global__ void gcn_agg_kernel(const unsigned char* __restrict__ A, const float* __restrict__ dinv,
                               const float* __restrict__ xw, const float* __restrict__ gcn_b,
                               float* __restrict__ cat, uint32_t* __restrict__ catblob) {
    int r = blockIdx.x;
    int b = r >> 10;
    const unsigned char* Arow = A + (long long)r * SEQ;
    __shared__ int   nbr[SEQ];
    __shared__ float wgt[SEQ];
    __shared__ float sbuf[DIM];
    __shared__ int cnt;
    int tid = threadIdx.x;
    if (tid == 0) cnt = 0;
    __syncthreads();
    for (int t = tid; t < SEQ; t += 256) {
        if (Arow[t]) {
            int p = atomicAdd(&cnt, 1);
            nbr[p] = t;
            wgt[p] = dinv[(b << 10) + t];
        }
    }
    __syncthreads();
    int n = cnt;
    float acc0 = 0.f, acc1 = 0.f, acc2 = 0.f;
    for (int i = 0; i < n; i++) {
        const float* row = xw + ((long)(b << 10) + nbr[i]) * DIM;
        float w = wgt[i];
        acc0 += w * row[tid];
        acc1 += w * row[tid + 256];
        acc2 += w * row[tid + 512];
    }
    float ws = dinv[r];
    long base = (long)r * (2 * DIM);
    float o0 = ws * acc0 + gcn_b[tid];
    float o1 = ws * acc1 + gcn_b[tid + 256];
    float o2 = ws * acc2 + gcn_b[tid + 512];
    cat[base + tid]       = o0;
    cat[base + tid + 256] = o1;
    cat[base + tid + 512] = o2;
    sbuf[tid] = o0; sbuf[tid + 256] = o1; sbuf[tid + 512] = o2;
    __syncthreads();
    long mblk = r >> 7;
    int rloc = r & 127;
    int im = rloc >> 4, row8 = (rloc >> 3) & 1, g = rloc & 7;
    for (int w = tid; w < 384; w += 256) {
        int kch = w >> 4, ikf = (w >> 3) & 1, k8 = (w >> 2) & 1, t = w & 3;
        long word = ((mblk * 48 + kch) * 2048) + im * 256 + ikf * 128
                  + (g * 4 + t) * 4 + 2 * k8 + row8;
        catblob[word] = pack_h2(sbuf[2 * w], sbuf[2 * w + 1]);
    }
}

// ---------------- gate + residual + layernorm: h fp32 + h-blob ----------------
__global__ void fuse_ln_kernel(const float* __restrict__ gatelin, const float* __restrict__ cat,
                               const float* __restrict__ hin, float* __restrict__ hout,
                               uint32_t* __restrict__ hblob,
                               const float* __restrict__ ln_scale, const float* __restrict__ ln_bias) {
    long r = blockIdx.x;
    int tid = threadIdx.x;
    __shared__ float red[256];
    __shared__ float sbuf[DIM];
    float f[3];
    #pragma unroll
    for (int i = 0; i < 3; i++) {
        int j = tid + 256 * i;
        float g  = gatelin[r * DIM + j];
        float gc = cat[r * (2 * DIM) + j];
        float at = cat[r * (2 * DIM) + DIM + j];
        float sg = 1.f / (1.f + fexp(-g));
        f[i] = sg * gc + (1.f - sg) * at + hin[r * DIM + j];
    }
    float s1 = f[0] + f[1] + f[2];
    red[tid] = s1; __syncthreads();
    #pragma unroll
    for (int o = 128; o > 0; o >>= 1) { if (tid < o) red[tid] += red[tid + o]; __syncthreads(); }
    float mu = red[0] * (1.f / DIM);
    __syncthreads();
    float s2 = 0.f;
    #pragma unroll
    for (int i = 0; i < 3; i++) { float d = f[i] - mu; s2 += d * d; }
    red[tid] = s2; __syncthreads();
    #pragma unroll
    for (int o = 128; o > 0; o >>= 1) { if (tid < o) red[tid] += red[tid + o]; __syncthreads(); }
    float var = red[0] * (1.f / DIM);
    float inv = rsqrtf(var + LN_EPS);
    #pragma unroll
    for (int i = 0; i < 3; i++) {
        int j = tid + 256 * i;
        float v = (f[i] - mu) * inv * ln_scale[j] + ln_bias[j];
        hout[r * DIM + j] = v;
        sbuf[j] = v;
    }
    __syncthreads();
    long mblk = r >> 7;
    int rloc = (int)(r & 127);
    int im = rloc >> 4, row8 = (rloc >> 3) & 1, g = rloc & 7;
    for (int w = tid; w < 384; w += 256) {
        int kch = w >> 4, ikf = (w >> 3) & 1, k8 = (w >> 2) & 1, t = w & 3;
        long word = ((mblk * 24 + kch) * 2048) + im * 256 + ikf * 128
                  + (g * 4 + t) * 4 + 2 * k8 + row8;
        hblob[word] = pack_h2(sbuf[2 * w], sbuf[2 * w + 1]);
    }
}

// ---------------- host helper ----------------
static void launch_mma(const uint32_t* Ap, const uint32_t* Wp, float* C, long ldc,
                       const float* bias, int M, int N, int K,
                       uint32_t* packBlob = nullptr, int packNch = 0, int packKchBase = 0) {
    dim3 grid(N / 128, M / 128, 1);
    mma_gemm<<<grid, 256>>>(Ap, Wp, C, ldc, bias, N / 128, C, ldc, bias, K / 32,
                            packBlob, packNch, packKchBase, nullptr);
}

extern "C" void kernel_launch(void* const* d_in, const int* in_sizes, int n_in,
                              void* d_out, int out_size) {
    const float* x          = (const float*)d_in[0];
    const float* gcn_w      = (const float*)d_in[1];
    const float* gcn_b      = (const float*)d_in[2];
    const float* attn_in_w  = (const float*)d_in[3];
    const float* attn_in_b  = (const float*)d_in[4];
    const float* attn_out_w = (const float*)d_in[5];
    const float* attn_out_b = (const float*)d_in[6];
    const float* gate_w     = (const float*)d_in[7];
    const float* gate_b     = (const float*)d_in[8];
    const float* ln_scale   = (const float*)d_in[9];
    const float* ln_bias    = (const float*)d_in[10];
    const float* proj_w     = (const float*)d_in[11];
    const float* proj_b     = (const float*)d_in[12];
    float* out = (float*)d_out;

    static cudaStream_t s_side = nullptr, s_w = nullptr;
    static cudaEvent_t ev_fork = nullptr, ev_wpack = nullptr;
    static cudaEvent_t ev_xw[NLAYERS], ev_agg[NLAYERS];
    if (!s_side) {
        cudaStreamCreateWithFlags(&s_side, cudaStreamNonBlocking);
        cudaStreamCreateWithFlags(&s_w, cudaStreamNonBlocking);
        cudaEventCreateWithFlags(&ev_fork, cudaEventDisableTiming);
        cudaEventCreateWithFlags(&ev_wpack, cudaEventDisableTiming);
        for (int l = 0; l < NLAYERS; l++) {
            cudaEventCreateWithFlags(&ev_xw[l], cudaEventDisableTiming);
            cudaEventCreateWithFlags(&ev_agg[l], cudaEventDisableTiming);
        }
    }

    float *p_h, *p_xw, *p_qkv, *p_scores, *p_cat, *p_gate, *p_dinv, *p_vt;
    uint32_t *p_wp, *p_ap;
    unsigned char* p_adj;
    int* p_topk;
    cudaGetSymbolAddress((void**)&p_h, g_h);
    cudaGetSymbolAddress((void**)&p_xw, g_xw);
    cudaGetSymbolAddress((void**)&p_qkv, g_qkv);
    cudaGetSymbolAddress((void**)&p_scores, g_scores);
    cudaGetSymbolAddress((void**)&p_cat, g_cat);
    cudaGetSymbolAddress((void**)&p_gate, g_gate);
    cudaGetSymbolAddress((void**)&p_dinv, g_dinv);
    cudaGetSymbolAddress((void**)&p_adj, g_adj);
    cudaGetSymbolAddress((void**)&p_topk, g_topk);
    cudaGetSymbolAddress((void**)&p_wp, g_wp);
    cudaGetSymbolAddress((void**)&p_ap, g_ap);
    cudaGetSymbolAddress((void**)&p_vt, g_vt);

    const float attn_scale = (float)(1.0 / sqrt((double)HDIM));

    // ---- fork: graph-construction chain on side stream ----
    cudaEventRecord(ev_fork, 0);
    cudaStreamWaitEvent(s_side, ev_fork, 0);
    sim_gemm<<<dim3(8, 8, BATCH), 256, 0, s_side>>>(x, p_scores);
    topk_warp_kernel<<<ROWS / 8, 256, 0, s_side>>>(p_scores, p_topk);
    zero_bytes_kernel<<<1024, 256, 0, s_side>>>(p_adj, (long long)BATCH * SEQ * SEQ);
    scatter_adj_kernel<<<(ROWS + 255) / 256, 256, 0, s_side>>>(p_topk, p_adj);
    degree_kernel<<<(ROWS + 255) / 256, 256, 0, s_side>>>(p_adj, p_dinv);

    // ---- weight-pack stream: everything not needed by the first fused GEMM ----
    cudaStreamWaitEvent(s_w, ev_fork, 0);
    for (int l = 1; l < NLAYERS; l++) {
        pack_weights_kernel<<<512, 256, 0, s_w>>>(gcn_w + (long)l * DIM * DIM, p_wp + WP_FUSED(l), DIM, DIM);
        pack_weights_kernel<<<512, 256, 0, s_w>>>(attn_in_w + (long)l * DIM * 3 * DIM,
                                                  p_wp + WP_FUSED(l) + 294912, 3 * DIM, DIM);
    }
    for (int l = 0; l < NLAYERS; l++) {
        pack_weights_kernel<<<512, 256, 0, s_w>>>(attn_out_w + (long)l * DIM * DIM, p_wp + WP_AOW(l), DIM, DIM);
        pack_weights_kernel<<<512, 256, 0, s_w>>>(gate_w + (long)l * 2 * DIM * DIM, p_wp + WP_GW(l), DIM, 2 * DIM);
    }
    pack_weights_kernel<<<512, 256, 0, s_w>>>(proj_w, p_wp + WP_PROJ, DIM, DIM);
    cudaEventRecord(ev_wpack, s_w);

    // ---- main stream: only layer-0 fused packs + x blob ----
    pack_weights_kernel<<<512, 256>>>(gcn_w, p_wp + WP_FUSED(0), DIM, DIM);
    pack_weights_kernel<<<512, 256>>>(attn_in_w, p_wp + WP_FUSED(0) + 294912, 3 * DIM, DIM);
    pack_act_kernel<<<dim3(24, 64), 256>>>(x, p_ap + AP_H, DIM);

    bool wjoined = false;
    for (int l = 0; l < NLAYERS; l++) {
        const float* gb  = gcn_b + (long)l * DIM;
        const float* aib = attn_in_b + (long)l * 3 * DIM;
        const float* aob = attn_out_b + (long)l * DIM;
        const float* gtb = gate_b + (long)l * DIM;
        const float* lns = ln_scale + (long)l * DIM;
        const float* lnb = ln_bias + (long)l * DIM;
        const float* hin = (l == 0) ? x : p_h;

        // fused: XW -> xw (0-5), QKV -> qkv (6-23), V also -> vt (epilogue)
        {
            dim3 grid(24, ROWS / 128, 1);
            mma_gemm<<<grid, 256>>>(p_ap + AP_H, p_wp + WP_FUSED(l),
                                    p_xw, DIM, gb, 6,
                                    p_qkv, 3 * DIM, aib,
                                    24, nullptr, 0, 0, p_vt);
        }
        cudaEventRecord(ev_xw[l], 0);

        // side stream: gcn_agg overlapped with attention path
        cudaStreamWaitEvent(s_side, ev_xw[l], 0);
        gcn_agg_kernel<<<ROWS, 256, 0, s_side>>>(p_adj, p_dinv, p_xw, gb, p_cat, p_ap + AP_CAT);
        cudaEventRecord(ev_agg[l], s_side);

        // main stream: flash attention (vt already emitted by fused GEMM)
        flash_kernel<<<dim3(1, 8, 64), 256>>>(p_qkv, p_vt, p_ap + AP_O, attn_scale);
        // join weight-pack stream before first use of AOW/GW/proj/fused(1,2)
        if (!wjoined) { cudaStreamWaitEvent(0, ev_wpack, 0); wjoined = true; }
        // attn_out GEMM: cat fp32 [:,768:1536] + cat blob kch 24-47
        launch_mma(p_ap + AP_O, p_wp + WP_AOW(l), p_cat + DIM, 2 * DIM, aob,
                   ROWS, DIM, DIM, p_ap + AP_CAT, 48, 24);

        // join: gate GEMM needs both cat halves
        cudaStreamWaitEvent(0, ev_agg[l], 0);
        launch_mma(p_ap + AP_CAT, p_wp + WP_GW(l), p_gate, DIM, gtb, ROWS, DIM, 2 * DIM);
        // h = LN(gate*gcn + (1-gate)*attn + hin) -> h fp32 + h blob
        fuse_ln_kernel<<<ROWS, 256>>>(p_gate, p_cat, hin, p_h, p_ap + AP_H, lns, lnb);
    }

    // out = h @ proj_w + proj_b
    launch_mma(p_ap + AP_H, p_wp + WP_PROJ, out, DIM, proj_b, ROWS, DIM, DIM);
}